// round 2
// baseline (speedup 1.0000x reference)
#include <cuda_runtime.h>
#include <math.h>

// Problem constants (fixed by the reference: B=2, S=2048, D=2048, H=16)
#define BATCH  2
#define SEQ    2048
#define DMODEL 2048
#define NHEAD  16
#define HDIM   128            // DMODEL / NHEAD
#define MROWS  (BATCH * SEQ)  // 4096

// -------- scratch (device globals: allocation-free) --------
__device__ float g_q[(size_t)BATCH * SEQ * DMODEL];
__device__ float g_k[(size_t)BATCH * SEQ * DMODEL];
__device__ float g_v[(size_t)BATCH * SEQ * DMODEL];
__device__ float g_ao[(size_t)BATCH * SEQ * DMODEL];

// ============================================================
// GEMM: C[M,N] = A[M,K] @ B[N,K]^T   (both K-major, "NT")
// Tiles: BM=128, BN=128, BK=16; 256 threads; 8x8 per thread.
// Double-buffered smem + register prefetch: 1 sync per K-slab.
// ============================================================
__global__ __launch_bounds__(256) void gemm_nt_kernel(
    const float* __restrict__ A, const float* __restrict__ B,
    float* __restrict__ C, int M, int N, int K)
{
    __shared__ float As[2][16][128];
    __shared__ float Bs[2][16][128];

    const int tid = threadIdx.x;
    const int tx = tid & 15;        // n-group
    const int ty = tid >> 4;        // m-group
    const int m0 = blockIdx.y * 128;
    const int n0 = blockIdx.x * 128;

    const int K4 = K >> 2;
    const float4* A4 = (const float4*)A;
    const float4* B4 = (const float4*)B;

    // this thread's two load slots: v = tid*2 + l, row = v>>2, k4 = v&3
    const int lrow0 = (tid * 2 + 0) >> 2, lk0 = (tid * 2 + 0) & 3;
    const int lrow1 = (tid * 2 + 1) >> 2, lk1 = (tid * 2 + 1) & 3;

    float acc[8][8];
    #pragma unroll
    for (int i = 0; i < 8; i++)
        #pragma unroll
        for (int j = 0; j < 8; j++) acc[i][j] = 0.f;

    // ---- preload slab 0 into buffer 0 ----
    {
        float4 a0 = A4[(size_t)(m0 + lrow0) * K4 + lk0];
        float4 a1 = A4[(size_t)(m0 + lrow1) * K4 + lk1];
        float4 b0 = B4[(size_t)(n0 + lrow0) * K4 + lk0];
        float4 b1 = B4[(size_t)(n0 + lrow1) * K4 + lk1];
        As[0][lk0*4+0][lrow0]=a0.x; As[0][lk0*4+1][lrow0]=a0.y;
        As[0][lk0*4+2][lrow0]=a0.z; As[0][lk0*4+3][lrow0]=a0.w;
        As[0][lk1*4+0][lrow1]=a1.x; As[0][lk1*4+1][lrow1]=a1.y;
        As[0][lk1*4+2][lrow1]=a1.z; As[0][lk1*4+3][lrow1]=a1.w;
        Bs[0][lk0*4+0][lrow0]=b0.x; Bs[0][lk0*4+1][lrow0]=b0.y;
        Bs[0][lk0*4+2][lrow0]=b0.z; Bs[0][lk0*4+3][lrow0]=b0.w;
        Bs[0][lk1*4+0][lrow1]=b1.x; Bs[0][lk1*4+1][lrow1]=b1.y;
        Bs[0][lk1*4+2][lrow1]=b1.z; Bs[0][lk1*4+3][lrow1]=b1.w;
    }
    __syncthreads();

    const int nslab = K >> 4;
    for (int s = 0; s < nslab; s++) {
        const int buf = s & 1;

        // prefetch slab s+1 into registers (overlaps with compute below)
        float4 pa0, pa1, pb0, pb1;
        const bool more = (s + 1 < nslab);
        if (more) {
            int kb = (s + 1) << 2;   // float4 offset of next slab
            pa0 = A4[(size_t)(m0 + lrow0) * K4 + kb + lk0];
            pa1 = A4[(size_t)(m0 + lrow1) * K4 + kb + lk1];
            pb0 = B4[(size_t)(n0 + lrow0) * K4 + kb + lk0];
            pb1 = B4[(size_t)(n0 + lrow1) * K4 + kb + lk1];
        }

        #pragma unroll
        for (int kk = 0; kk < 16; kk++) {
            float ra[8], rb[8];
            float4 a0 = *(const float4*)&As[buf][kk][ty * 8];
            float4 a1 = *(const float4*)&As[buf][kk][ty * 8 + 4];
            float4 b0 = *(const float4*)&Bs[buf][kk][tx * 8];
            float4 b1 = *(const float4*)&Bs[buf][kk][tx * 8 + 4];
            ra[0]=a0.x; ra[1]=a0.y; ra[2]=a0.z; ra[3]=a0.w;
            ra[4]=a1.x; ra[5]=a1.y; ra[6]=a1.z; ra[7]=a1.w;
            rb[0]=b0.x; rb[1]=b0.y; rb[2]=b0.z; rb[3]=b0.w;
            rb[4]=b1.x; rb[5]=b1.y; rb[6]=b1.z; rb[7]=b1.w;
            #pragma unroll
            for (int i = 0; i < 8; i++)
                #pragma unroll
                for (int j = 0; j < 8; j++)
                    acc[i][j] = fmaf(ra[i], rb[j], acc[i][j]);
        }

        if (more) {
            const int nb = buf ^ 1;   // disjoint buffer: no sync needed before write
            As[nb][lk0*4+0][lrow0]=pa0.x; As[nb][lk0*4+1][lrow0]=pa0.y;
            As[nb][lk0*4+2][lrow0]=pa0.z; As[nb][lk0*4+3][lrow0]=pa0.w;
            As[nb][lk1*4+0][lrow1]=pa1.x; As[nb][lk1*4+1][lrow1]=pa1.y;
            As[nb][lk1*4+2][lrow1]=pa1.z; As[nb][lk1*4+3][lrow1]=pa1.w;
            Bs[nb][lk0*4+0][lrow0]=pb0.x; Bs[nb][lk0*4+1][lrow0]=pb0.y;
            Bs[nb][lk0*4+2][lrow0]=pb0.z; Bs[nb][lk0*4+3][lrow0]=pb0.w;
            Bs[nb][lk1*4+0][lrow1]=pb1.x; Bs[nb][lk1*4+1][lrow1]=pb1.y;
            Bs[nb][lk1*4+2][lrow1]=pb1.z; Bs[nb][lk1*4+3][lrow1]=pb1.w;
            __syncthreads();
        }
    }

    // Store 8x8 per thread, vectorized
    #pragma unroll
    for (int i = 0; i < 8; i++) {
        size_t crow = (size_t)(m0 + ty * 8 + i) * N + n0 + tx * 8;
        float4 c0 = make_float4(acc[i][0], acc[i][1], acc[i][2], acc[i][3]);
        float4 c1 = make_float4(acc[i][4], acc[i][5], acc[i][6], acc[i][7]);
        *(float4*)&C[crow]     = c0;
        *(float4*)&C[crow + 4] = c1;
    }
}

// ============================================================
// Flash attention (causal, fp32): one block per (q_tile, head, batch)
// BQ=64, BKV=64, hd=128, 256 threads.
// Smem: Qs/Ks/Vs padded rows of 132 floats; scores 64x65.
// ============================================================
#define BQ  64
#define BKV 64
#define RSF 132          // row stride (floats) for Q/K/V tiles
#define RS4 33           // row stride (float4)
#define SST 65           // score row stride (floats)

#define FLASH_SMEM_FLOATS (3 * BQ * RSF + BQ * SST + 3 * BQ)
#define FLASH_SMEM_BYTES  (FLASH_SMEM_FLOATS * 4)

__global__ __launch_bounds__(256) void flash_attn_kernel(
    const float* __restrict__ q, const float* __restrict__ k,
    const float* __restrict__ v, float* __restrict__ o)
{
    extern __shared__ float sm[];
    float* Qs    = sm;                       // 64*132
    float* Ks    = Qs + BQ * RSF;            // 64*132
    float* Vs    = Ks + BQ * RSF;            // 64*132
    float* Ss    = Vs + BQ * RSF;            // 64*65
    float* row_m = Ss + BQ * SST;            // 64
    float* row_l = row_m + BQ;               // 64
    float* row_a = row_l + BQ;               // 64

    const int tid = threadIdx.x;
    const int qt = blockIdx.x;               // 0..31
    const int h  = blockIdx.y;
    const int b  = blockIdx.z;
    const int q0 = qt * BQ;

    const size_t gbase4 = (((size_t)b * SEQ * DMODEL) + (size_t)h * HDIM) >> 2;
    const int D4 = DMODEL >> 2;
    const float4* q4g = (const float4*)q;
    const float4* k4g = (const float4*)k;
    const float4* v4g = (const float4*)v;

    // load Q tile (2048 float4; 8 per thread), swizzle into padded rows
    #pragma unroll
    for (int l = 0; l < 8; l++) {
        int ve  = tid + l * 256;
        int row = ve >> 5;
        int c4  = ve & 31;
        ((float4*)Qs)[row * RS4 + c4] = q4g[gbase4 + (size_t)(q0 + row) * D4 + c4];
    }
    if (tid < BQ) { row_m[tid] = -1e30f; row_l[tid] = 0.f; }

    // per-thread output tile: rows r0..r0+3, cols c0..c0+7
    const int rg = tid >> 4;     // 0..15
    const int cg = tid & 15;     // 0..15
    const int r0 = rg * 4;
    const int c0 = cg * 8;
    float oa[4][8];
    #pragma unroll
    for (int i = 0; i < 4; i++)
        #pragma unroll
        for (int c = 0; c < 8; c++) oa[i][c] = 0.f;

    const float scale = 0.08838834764831845f;  // 1/sqrt(128)

    for (int kt = 0; kt <= qt; kt++) {
        const int k0 = kt * BKV;
        __syncthreads();   // protect Ks/Vs from previous iteration's readers
        #pragma unroll
        for (int l = 0; l < 8; l++) {
            int ve  = tid + l * 256;
            int row = ve >> 5;
            int c4  = ve & 31;
            ((float4*)Ks)[row * RS4 + c4] = k4g[gbase4 + (size_t)(k0 + row) * D4 + c4];
            ((float4*)Vs)[row * RS4 + c4] = v4g[gbase4 + (size_t)(k0 + row) * D4 + c4];
        }
        __syncthreads();

        // --- scores: rows r0..r0+3, cols j = cg + 16*jj ---
        float sacc[4][4];
        #pragma unroll
        for (int i = 0; i < 4; i++)
            #pragma unroll
            for (int j = 0; j < 4; j++) sacc[i][j] = 0.f;

        const float4* Q4 = (const float4*)Qs;
        const float4* K4 = (const float4*)Ks;
        #pragma unroll 8
        for (int d4 = 0; d4 < 32; d4++) {
            float4 qv[4], kv[4];
            #pragma unroll
            for (int i = 0; i < 4; i++) qv[i] = Q4[(r0 + i) * RS4 + d4];
            #pragma unroll
            for (int j = 0; j < 4; j++) kv[j] = K4[(cg + 16 * j) * RS4 + d4];
            #pragma unroll
            for (int i = 0; i < 4; i++)
                #pragma unroll
                for (int j = 0; j < 4; j++) {
                    sacc[i][j] = fmaf(qv[i].x, kv[j].x, sacc[i][j]);
                    sacc[i][j] = fmaf(qv[i].y, kv[j].y, sacc[i][j]);
                    sacc[i][j] = fmaf(qv[i].z, kv[j].z, sacc[i][j]);
                    sacc[i][j] = fmaf(qv[i].w, kv[j].w, sacc[i][j]);
                }
        }
        #pragma unroll
        for (int i = 0; i < 4; i++)
            #pragma unroll
            for (int j = 0; j < 4; j++) {
                int jj = cg + 16 * j;
                float s = sacc[i][j] * scale;
                if (k0 + jj > q0 + r0 + i) s = -1e30f;   // causal mask
                Ss[(r0 + i) * SST + jj] = s;
            }
        __syncthreads();

        // --- online softmax: one thread per row ---
        if (tid < BQ) {
            const int r = tid;
            float mo = row_m[r];
            float mx = mo;
            #pragma unroll 8
            for (int j = 0; j < BKV; j++) mx = fmaxf(mx, Ss[r * SST + j]);
            float al = __expf(mo - mx);
            float l  = row_l[r] * al;
            #pragma unroll 8
            for (int j = 0; j < BKV; j++) {
                float p = __expf(Ss[r * SST + j] - mx);
                Ss[r * SST + j] = p;
                l += p;
            }
            row_m[r] = mx; row_l[r] = l; row_a[r] = al;
        }
        __syncthreads();

        // --- O update: oa = oa*alpha + P @ V ---
        float al[4];
        #pragma unroll
        for (int i = 0; i < 4; i++) al[i] = row_a[r0 + i];
        #pragma unroll
        for (int i = 0; i < 4; i++)
            #pragma unroll
            for (int c = 0; c < 8; c++) oa[i][c] *= al[i];

        const float4* V4 = (const float4*)Vs;
        #pragma unroll 8
        for (int j = 0; j < BKV; j++) {
            float p[4];
            #pragma unroll
            for (int i = 0; i < 4; i++) p[i] = Ss[(r0 + i) * SST + j];
            float4 v0 = V4[j * RS4 + cg * 2];
            float4 v1 = V4[j * RS4 + cg * 2 + 1];
            #pragma unroll
            for (int i = 0; i < 4; i++) {
                oa[i][0] = fmaf(p[i], v0.x, oa[i][0]);
                oa[i][1] = fmaf(p[i], v0.y, oa[i][1]);
                oa[i][2] = fmaf(p[i], v0.z, oa[i][2]);
                oa[i][3] = fmaf(p[i], v0.w, oa[i][3]);
                oa[i][4] = fmaf(p[i], v1.x, oa[i][4]);
                oa[i][5] = fmaf(p[i], v1.y, oa[i][5]);
                oa[i][6] = fmaf(p[i], v1.z, oa[i][6]);
                oa[i][7] = fmaf(p[i], v1.w, oa[i][7]);
            }
        }
    }

    // finalize: divide by l, store to [B,S,D] layout at (b, q0+r, h*HD + c0..)
    float4* o4 = (float4*)o;
    #pragma unroll
    for (int i = 0; i < 4; i++) {
        float inv = 1.0f / row_l[r0 + i];
        float4 r0v = make_float4(oa[i][0]*inv, oa[i][1]*inv, oa[i][2]*inv, oa[i][3]*inv);
        float4 r1v = make_float4(oa[i][4]*inv, oa[i][5]*inv, oa[i][6]*inv, oa[i][7]*inv);
        size_t oi = gbase4 + (size_t)(q0 + r0 + i) * D4 + (c0 >> 2);
        o4[oi]     = r0v;
        o4[oi + 1] = r1v;
    }
}

// ============================================================
// launcher
// ============================================================
extern "C" void kernel_launch(void* const* d_in, const int* in_sizes, int n_in,
                              void* d_out, int out_size)
{
    const float* x  = (const float*)d_in[0];
    const float* Wq = (const float*)d_in[1];
    const float* Wk = (const float*)d_in[2];
    const float* Wv = (const float*)d_in[3];
    const float* Wp = (const float*)d_in[4];
    float* out = (float*)d_out;

    void *pq, *pk, *pv, *pa;
    cudaGetSymbolAddress(&pq, g_q);
    cudaGetSymbolAddress(&pk, g_k);
    cudaGetSymbolAddress(&pv, g_v);
    cudaGetSymbolAddress(&pa, g_ao);

    cudaFuncSetAttribute(flash_attn_kernel,
                         cudaFuncAttributeMaxDynamicSharedMemorySize,
                         FLASH_SMEM_BYTES);

    dim3 gemm_grid(DMODEL / 128, MROWS / 128);   // (16, 32)
    dim3 gemm_blk(256);

    // QKV projections: q = x @ Wq^T, etc.
    gemm_nt_kernel<<<gemm_grid, gemm_blk>>>(x, Wq, (float*)pq, MROWS, DMODEL, DMODEL);
    gemm_nt_kernel<<<gemm_grid, gemm_blk>>>(x, Wk, (float*)pk, MROWS, DMODEL, DMODEL);
    gemm_nt_kernel<<<gemm_grid, gemm_blk>>>(x, Wv, (float*)pv, MROWS, DMODEL, DMODEL);

    // causal flash attention
    dim3 fgrid(SEQ / BQ, NHEAD, BATCH);          // (32, 16, 2)
    flash_attn_kernel<<<fgrid, 256, FLASH_SMEM_BYTES>>>(
        (const float*)pq, (const float*)pk, (const float*)pv, (float*)pa);

    // output projection: out = attn @ Wp^T
    gemm_nt_kernel<<<gemm_grid, gemm_blk>>>((const float*)pa, Wp, out, MROWS, DMODEL, DMODEL);
}

// round 4
// speedup vs baseline: 1.8995x; 1.8995x over previous
#include <cuda_runtime.h>
#include <cuda_bf16.h>
#include <stdint.h>
#include <math.h>

// Problem constants (fixed): B=2, S=2048, D=2048, H=16
#define BATCH  2
#define SEQ    2048
#define DMODEL 2048
#define NHEAD  16
#define HDIM   128
#define MROWS  (BATCH * SEQ)   // 4096

// ================= scratch (device globals: allocation-free) =================
__device__ float g_q [(size_t)MROWS * DMODEL];
__device__ float g_k [(size_t)MROWS * DMODEL];
__device__ float g_v [(size_t)MROWS * DMODEL];
__device__ float g_ao[(size_t)MROWS * DMODEL];

__device__ __nv_bfloat16 g_xhi [(size_t)MROWS * DMODEL];
__device__ __nv_bfloat16 g_xlo [(size_t)MROWS * DMODEL];
__device__ __nv_bfloat16 g_aohi[(size_t)MROWS * DMODEL];
__device__ __nv_bfloat16 g_aolo[(size_t)MROWS * DMODEL];
__device__ __nv_bfloat16 g_wqhi[(size_t)DMODEL * DMODEL];
__device__ __nv_bfloat16 g_wqlo[(size_t)DMODEL * DMODEL];
__device__ __nv_bfloat16 g_wkhi[(size_t)DMODEL * DMODEL];
__device__ __nv_bfloat16 g_wklo[(size_t)DMODEL * DMODEL];
__device__ __nv_bfloat16 g_wvhi[(size_t)DMODEL * DMODEL];
__device__ __nv_bfloat16 g_wvlo[(size_t)DMODEL * DMODEL];
__device__ __nv_bfloat16 g_wphi[(size_t)DMODEL * DMODEL];
__device__ __nv_bfloat16 g_wplo[(size_t)DMODEL * DMODEL];

// ================= PTX helpers (baseline features only — no 'a' gating) ======
__device__ __forceinline__ uint32_t smem_u32(const void* p) {
    uint32_t a;
    asm("{ .reg .u64 t; cvta.to.shared.u64 t, %1; cvt.u32.u64 %0, t; }" : "=r"(a) : "l"(p));
    return a;
}
__device__ __forceinline__ void cp_async16(uint32_t dst, const void* src) {
    asm volatile("cp.async.cg.shared.global [%0], [%1], 16;" :: "r"(dst), "l"(src) : "memory");
}
__device__ __forceinline__ void cp_commit() {
    asm volatile("cp.async.commit_group;" ::: "memory");
}
__device__ __forceinline__ void cp_wait1() {
    asm volatile("cp.async.wait_group 1;" ::: "memory");
}
__device__ __forceinline__ void cp_wait0() {
    asm volatile("cp.async.wait_group 0;" ::: "memory");
}
__device__ __forceinline__ void ldm_x4(uint32_t& r0, uint32_t& r1, uint32_t& r2, uint32_t& r3,
                                       uint32_t addr) {
    asm volatile("ldmatrix.sync.aligned.m8n8.x4.shared.b16 {%0,%1,%2,%3}, [%4];"
                 : "=r"(r0), "=r"(r1), "=r"(r2), "=r"(r3) : "r"(addr));
}
__device__ __forceinline__ void mma_bf16(float* c, const uint32_t* a, const uint32_t* b) {
    asm volatile("mma.sync.aligned.m16n8k16.row.col.f32.bf16.bf16.f32 "
                 "{%0,%1,%2,%3}, {%4,%5,%6,%7}, {%8,%9}, {%0,%1,%2,%3};"
                 : "+f"(c[0]), "+f"(c[1]), "+f"(c[2]), "+f"(c[3])
                 : "r"(a[0]), "r"(a[1]), "r"(a[2]), "r"(a[3]), "r"(b[0]), "r"(b[1]));
}

// ================= split kernel: fp32 -> (hi, lo) bf16 =================
__global__ __launch_bounds__(256) void split_kernel(
    const float* __restrict__ src, __nv_bfloat16* __restrict__ hi,
    __nv_bfloat16* __restrict__ lo, int n4)
{
    int i = blockIdx.x * blockDim.x + threadIdx.x;
    if (i >= n4) return;
    float4 v = ((const float4*)src)[i];
    __nv_bfloat16 h0 = __float2bfloat16(v.x), h1 = __float2bfloat16(v.y);
    __nv_bfloat16 h2 = __float2bfloat16(v.z), h3 = __float2bfloat16(v.w);
    __nv_bfloat16 l0 = __float2bfloat16(v.x - __bfloat162float(h0));
    __nv_bfloat16 l1 = __float2bfloat16(v.y - __bfloat162float(h1));
    __nv_bfloat16 l2 = __float2bfloat16(v.z - __bfloat162float(h2));
    __nv_bfloat16 l3 = __float2bfloat16(v.w - __bfloat162float(h3));
    __nv_bfloat162* hp = (__nv_bfloat162*)hi;
    __nv_bfloat162* lp = (__nv_bfloat162*)lo;
    hp[i * 2 + 0] = __nv_bfloat162(h0, h1);
    hp[i * 2 + 1] = __nv_bfloat162(h2, h3);
    lp[i * 2 + 0] = __nv_bfloat162(l0, l1);
    lp[i * 2 + 1] = __nv_bfloat162(l2, l3);
}

// ================= mma.sync GEMM: C[M,N] = A[M,K] @ B[N,K]^T ==================
// bf16x3 split: C = Ahi*Bhi + Ahi*Blo + Alo*Bhi (fp32 accum in registers).
// CTA tile 128x128, BK=64, 256 threads (8 warps, warp tile 32x64).
// cp.async double-buffered smem; SW128 swizzle; ldmatrix.x4 operand loads.
#define GBK        64
#define TILE_B     (128 * 128)                 // bytes per tile (128 rows x 128B)
#define STAGE_B    (4 * TILE_B)                // Ahi,Alo,Bhi,Blo
#define GEMM_SMEM  (2 * STAGE_B)               // 131072 B

// tile offsets within a stage
#define T_AHI 0
#define T_ALO (1 * TILE_B)
#define T_BHI (2 * TILE_B)
#define T_BLO (3 * TILE_B)

__global__ __launch_bounds__(256) void gemm_bf16x3_kernel(
    const __nv_bfloat16* __restrict__ Ahi, const __nv_bfloat16* __restrict__ Alo,
    const __nv_bfloat16* __restrict__ Bhi, const __nv_bfloat16* __restrict__ Blo,
    float* __restrict__ C, int M, int N, int K)
{
    extern __shared__ char smem[];
    const uint32_t sb = smem_u32(smem);
    const int tid = threadIdx.x;
    const int wid = tid >> 5;
    const int l   = tid & 31;
    const int wm  = wid & 3;       // 4 warp-rows of 32
    const int wn  = wid >> 2;      // 2 warp-cols of 64
    const int m0  = blockIdx.y * 128;
    const int n0  = blockIdx.x * 128;

    // ---- per-thread cp.async source/dst slots (4 chunks per tile per thread) ----
    // idx = tid + i*256 (i<4): row = idx>>3 (0..127), c16 = idx&7
    // dst byte = row*128 + (c16 ^ (row&7))*16 ; src elem = row*K + c*64 + c16*8
    int lrow[4], ldst[4];
    #pragma unroll
    for (int i = 0; i < 4; i++) {
        int idx = tid + i * 256;
        int row = idx >> 3, c16 = idx & 7;
        lrow[i] = row;
        ldst[i] = row * 128 + ((c16 ^ (row & 7)) << 4);
    }

    const __nv_bfloat16* gA[2] = { Ahi, Alo };
    const __nv_bfloat16* gB[2] = { Bhi, Blo };

    auto issue_stage = [&](int c, int buf) {
        uint32_t s0 = sb + buf * STAGE_B;
        #pragma unroll
        for (int i = 0; i < 4; i++) {
            int row = lrow[i];
            int koff = c * GBK + ((tid + i * 256) & 7) * 8;
            cp_async16(s0 + T_AHI + ldst[i], gA[0] + (size_t)(m0 + row) * K + koff);
            cp_async16(s0 + T_ALO + ldst[i], gA[1] + (size_t)(m0 + row) * K + koff);
            cp_async16(s0 + T_BHI + ldst[i], gB[0] + (size_t)(n0 + row) * K + koff);
            cp_async16(s0 + T_BLO + ldst[i], gB[1] + (size_t)(n0 + row) * K + koff);
        }
        cp_commit();
    };

    // ---- ldmatrix lane-address precompute ----
    // A frag (m16k16) at warp row mr, k16 step kk:
    //   lane row = mr + (l&15); c16 = kk*2 + (l>>4)
    const int a_rowoff = (l & 15);
    const int a_c16off = (l >> 4);          // 0 or 1
    // B frag-pair (n16 x k16) at col nb, step kk:
    //   lane row = nb + (l&7) + ((l&16)>>1); c16 = kk*2 + ((l>>3)&1)
    const int b_rowoff = (l & 7) | ((l & 16) >> 1);
    const int b_c16off = (l >> 3) & 1;

    float acc[2][8][4];
    #pragma unroll
    for (int mi = 0; mi < 2; mi++)
        #pragma unroll
        for (int nj = 0; nj < 8; nj++)
            #pragma unroll
            for (int t = 0; t < 4; t++) acc[mi][nj][t] = 0.f;

    const int nchunks = K / GBK;   // 32
    issue_stage(0, 0);
    issue_stage(1, 1);

    for (int c = 0; c < nchunks; c++) {
        const int buf = c & 1;
        if (c < nchunks - 2) cp_wait1(); else cp_wait0();
        __syncthreads();

        const uint32_t s0 = sb + buf * STAGE_B;
        #pragma unroll
        for (int kk = 0; kk < 4; kk++) {
            // ---- load A fragments (hi & lo), 2 m-frags each ----
            uint32_t ahi[2][4], alo[2][4];
            #pragma unroll
            for (int mi = 0; mi < 2; mi++) {
                int row = wm * 32 + mi * 16 + a_rowoff;
                int c16 = kk * 2 + a_c16off;
                uint32_t ad = s0 + row * 128 + ((c16 ^ (row & 7)) << 4);
                ldm_x4(ahi[mi][0], ahi[mi][1], ahi[mi][2], ahi[mi][3], ad + T_AHI);
                ldm_x4(alo[mi][0], alo[mi][1], alo[mi][2], alo[mi][3], ad + T_ALO);
            }
            // ---- load B fragments (hi & lo), 8 n-frags each (4 x4-ldmatrix) ----
            uint32_t bhi[8][2], blo[8][2];
            #pragma unroll
            for (int p = 0; p < 4; p++) {          // n16 pair p -> frags 2p, 2p+1
                int row = wn * 64 + p * 16 + b_rowoff;
                int c16 = kk * 2 + b_c16off;
                uint32_t ad = s0 + row * 128 + ((c16 ^ (row & 7)) << 4);
                ldm_x4(bhi[2*p][0], bhi[2*p][1], bhi[2*p+1][0], bhi[2*p+1][1], ad + T_BHI);
                ldm_x4(blo[2*p][0], blo[2*p][1], blo[2*p+1][0], blo[2*p+1][1], ad + T_BLO);
            }
            // ---- 3-term mma ----
            #pragma unroll
            for (int mi = 0; mi < 2; mi++)
                #pragma unroll
                for (int nj = 0; nj < 8; nj++) {
                    mma_bf16(acc[mi][nj], ahi[mi], bhi[nj]);
                    mma_bf16(acc[mi][nj], ahi[mi], blo[nj]);
                    mma_bf16(acc[mi][nj], alo[mi], bhi[nj]);
                }
        }
        __syncthreads();
        if (c + 2 < nchunks) issue_stage(c + 2, buf);
    }

    // ---- epilogue: fragment layout c0:(r, 2q) c1:(r, 2q+1) c2:(r+8, 2q) c3 ----
    const int er = l >> 2;          // 0..7
    const int ec = (l & 3) * 2;     // 0,2,4,6
    #pragma unroll
    for (int mi = 0; mi < 2; mi++) {
        int grow = m0 + wm * 32 + mi * 16 + er;
        #pragma unroll
        for (int nj = 0; nj < 8; nj++) {
            int gcol = n0 + wn * 64 + nj * 8 + ec;
            *(float2*)&C[(size_t)grow * N + gcol]       = make_float2(acc[mi][nj][0], acc[mi][nj][1]);
            *(float2*)&C[(size_t)(grow + 8) * N + gcol] = make_float2(acc[mi][nj][2], acc[mi][nj][3]);
        }
    }
}

// ============================================================
// Flash attention (causal, fp32) — unchanged from passing baseline
// ============================================================
#define BQ  64
#define BKV 64
#define RSF 132
#define RS4 33
#define SST 65

#define FLASH_SMEM_FLOATS (3 * BQ * RSF + BQ * SST + 3 * BQ)
#define FLASH_SMEM_BYTES  (FLASH_SMEM_FLOATS * 4)

__global__ __launch_bounds__(256) void flash_attn_kernel(
    const float* __restrict__ q, const float* __restrict__ k,
    const float* __restrict__ v, float* __restrict__ o)
{
    extern __shared__ float sm[];
    float* Qs    = sm;
    float* Ks    = Qs + BQ * RSF;
    float* Vs    = Ks + BQ * RSF;
    float* Ss    = Vs + BQ * RSF;
    float* row_m = Ss + BQ * SST;
    float* row_l = row_m + BQ;
    float* row_a = row_l + BQ;

    const int tid = threadIdx.x;
    const int qt = blockIdx.x;
    const int h  = blockIdx.y;
    const int b  = blockIdx.z;
    const int q0 = qt * BQ;

    const size_t gbase4 = (((size_t)b * SEQ * DMODEL) + (size_t)h * HDIM) >> 2;
    const int D4 = DMODEL >> 2;
    const float4* q4g = (const float4*)q;
    const float4* k4g = (const float4*)k;
    const float4* v4g = (const float4*)v;

    #pragma unroll
    for (int l = 0; l < 8; l++) {
        int ve  = tid + l * 256;
        int row = ve >> 5;
        int c4  = ve & 31;
        ((float4*)Qs)[row * RS4 + c4] = q4g[gbase4 + (size_t)(q0 + row) * D4 + c4];
    }
    if (tid < BQ) { row_m[tid] = -1e30f; row_l[tid] = 0.f; }

    const int rg = tid >> 4;
    const int cg = tid & 15;
    const int r0 = rg * 4;
    const int c0 = cg * 8;
    float oa[4][8];
    #pragma unroll
    for (int i = 0; i < 4; i++)
        #pragma unroll
        for (int c = 0; c < 8; c++) oa[i][c] = 0.f;

    const float scale = 0.08838834764831845f;

    for (int kt = 0; kt <= qt; kt++) {
        const int k0 = kt * BKV;
        __syncthreads();
        #pragma unroll
        for (int l = 0; l < 8; l++) {
            int ve  = tid + l * 256;
            int row = ve >> 5;
            int c4  = ve & 31;
            ((float4*)Ks)[row * RS4 + c4] = k4g[gbase4 + (size_t)(k0 + row) * D4 + c4];
            ((float4*)Vs)[row * RS4 + c4] = v4g[gbase4 + (size_t)(k0 + row) * D4 + c4];
        }
        __syncthreads();

        float sacc[4][4];
        #pragma unroll
        for (int i = 0; i < 4; i++)
            #pragma unroll
            for (int j = 0; j < 4; j++) sacc[i][j] = 0.f;

        const float4* Q4 = (const float4*)Qs;
        const float4* K4 = (const float4*)Ks;
        #pragma unroll 8
        for (int d4 = 0; d4 < 32; d4++) {
            float4 qv[4], kv[4];
            #pragma unroll
            for (int i = 0; i < 4; i++) qv[i] = Q4[(r0 + i) * RS4 + d4];
            #pragma unroll
            for (int j = 0; j < 4; j++) kv[j] = K4[(cg + 16 * j) * RS4 + d4];
            #pragma unroll
            for (int i = 0; i < 4; i++)
                #pragma unroll
                for (int j = 0; j < 4; j++) {
                    sacc[i][j] = fmaf(qv[i].x, kv[j].x, sacc[i][j]);
                    sacc[i][j] = fmaf(qv[i].y, kv[j].y, sacc[i][j]);
                    sacc[i][j] = fmaf(qv[i].z, kv[j].z, sacc[i][j]);
                    sacc[i][j] = fmaf(qv[i].w, kv[j].w, sacc[i][j]);
                }
        }
        #pragma unroll
        for (int i = 0; i < 4; i++)
            #pragma unroll
            for (int j = 0; j < 4; j++) {
                int jj = cg + 16 * j;
                float s = sacc[i][j] * scale;
                if (k0 + jj > q0 + r0 + i) s = -1e30f;
                Ss[(r0 + i) * SST + jj] = s;
            }
        __syncthreads();

        if (tid < BQ) {
            const int r = tid;
            float mo = row_m[r];
            float mx = mo;
            #pragma unroll 8
            for (int j = 0; j < BKV; j++) mx = fmaxf(mx, Ss[r * SST + j]);
            float al = __expf(mo - mx);
            float l  = row_l[r] * al;
            #pragma unroll 8
            for (int j = 0; j < BKV; j++) {
                float p = __expf(Ss[r * SST + j] - mx);
                Ss[r * SST + j] = p;
                l += p;
            }
            row_m[r] = mx; row_l[r] = l; row_a[r] = al;
        }
        __syncthreads();

        float al[4];
        #pragma unroll
        for (int i = 0; i < 4; i++) al[i] = row_a[r0 + i];
        #pragma unroll
        for (int i = 0; i < 4; i++)
            #pragma unroll
            for (int c = 0; c < 8; c++) oa[i][c] *= al[i];

        const float4* V4 = (const float4*)Vs;
        #pragma unroll 8
        for (int j = 0; j < BKV; j++) {
            float p[4];
            #pragma unroll
            for (int i = 0; i < 4; i++) p[i] = Ss[(r0 + i) * SST + j];
            float4 v0 = V4[j * RS4 + cg * 2];
            float4 v1 = V4[j * RS4 + cg * 2 + 1];
            #pragma unroll
            for (int i = 0; i < 4; i++) {
                oa[i][0] = fmaf(p[i], v0.x, oa[i][0]);
                oa[i][1] = fmaf(p[i], v0.y, oa[i][1]);
                oa[i][2] = fmaf(p[i], v0.z, oa[i][2]);
                oa[i][3] = fmaf(p[i], v0.w, oa[i][3]);
                oa[i][4] = fmaf(p[i], v1.x, oa[i][4]);
                oa[i][5] = fmaf(p[i], v1.y, oa[i][5]);
                oa[i][6] = fmaf(p[i], v1.z, oa[i][6]);
                oa[i][7] = fmaf(p[i], v1.w, oa[i][7]);
            }
        }
    }

    float4* o4 = (float4*)o;
    #pragma unroll
    for (int i = 0; i < 4; i++) {
        float inv = 1.0f / row_l[r0 + i];
        float4 r0v = make_float4(oa[i][0]*inv, oa[i][1]*inv, oa[i][2]*inv, oa[i][3]*inv);
        float4 r1v = make_float4(oa[i][4]*inv, oa[i][5]*inv, oa[i][6]*inv, oa[i][7]*inv);
        size_t oi = gbase4 + (size_t)(q0 + r0 + i) * D4 + (c0 >> 2);
        o4[oi]     = r0v;
        o4[oi + 1] = r1v;
    }
}

// ============================================================
// launcher
// ============================================================
extern "C" void kernel_launch(void* const* d_in, const int* in_sizes, int n_in,
                              void* d_out, int out_size)
{
    const float* x  = (const float*)d_in[0];
    const float* Wq = (const float*)d_in[1];
    const float* Wk = (const float*)d_in[2];
    const float* Wv = (const float*)d_in[3];
    const float* Wp = (const float*)d_in[4];
    float* out = (float*)d_out;

    void *pq, *pk, *pv, *pa;
    cudaGetSymbolAddress(&pq, g_q);
    cudaGetSymbolAddress(&pk, g_k);
    cudaGetSymbolAddress(&pv, g_v);
    cudaGetSymbolAddress(&pa, g_ao);

    void *xhi, *xlo, *aohi, *aolo;
    void *wqhi, *wqlo, *wkhi, *wklo, *wvhi, *wvlo, *wphi, *wplo;
    cudaGetSymbolAddress(&xhi,  g_xhi);  cudaGetSymbolAddress(&xlo,  g_xlo);
    cudaGetSymbolAddress(&aohi, g_aohi); cudaGetSymbolAddress(&aolo, g_aolo);
    cudaGetSymbolAddress(&wqhi, g_wqhi); cudaGetSymbolAddress(&wqlo, g_wqlo);
    cudaGetSymbolAddress(&wkhi, g_wkhi); cudaGetSymbolAddress(&wklo, g_wklo);
    cudaGetSymbolAddress(&wvhi, g_wvhi); cudaGetSymbolAddress(&wvlo, g_wvlo);
    cudaGetSymbolAddress(&wphi, g_wphi); cudaGetSymbolAddress(&wplo, g_wplo);

    cudaFuncSetAttribute(flash_attn_kernel,
                         cudaFuncAttributeMaxDynamicSharedMemorySize, FLASH_SMEM_BYTES);
    cudaFuncSetAttribute(gemm_bf16x3_kernel,
                         cudaFuncAttributeMaxDynamicSharedMemorySize, GEMM_SMEM);

    const int nx4 = (MROWS * DMODEL) / 4;
    const int nw4 = (DMODEL * DMODEL) / 4;

    split_kernel<<<(nx4 + 255) / 256, 256>>>(x,  (__nv_bfloat16*)xhi,  (__nv_bfloat16*)xlo,  nx4);
    split_kernel<<<(nw4 + 255) / 256, 256>>>(Wq, (__nv_bfloat16*)wqhi, (__nv_bfloat16*)wqlo, nw4);
    split_kernel<<<(nw4 + 255) / 256, 256>>>(Wk, (__nv_bfloat16*)wkhi, (__nv_bfloat16*)wklo, nw4);
    split_kernel<<<(nw4 + 255) / 256, 256>>>(Wv, (__nv_bfloat16*)wvhi, (__nv_bfloat16*)wvlo, nw4);
    split_kernel<<<(nw4 + 255) / 256, 256>>>(Wp, (__nv_bfloat16*)wphi, (__nv_bfloat16*)wplo, nw4);

    dim3 ggrid(DMODEL / 128, MROWS / 128);   // (16, 32)

    gemm_bf16x3_kernel<<<ggrid, 256, GEMM_SMEM>>>(
        (const __nv_bfloat16*)xhi, (const __nv_bfloat16*)xlo,
        (const __nv_bfloat16*)wqhi, (const __nv_bfloat16*)wqlo,
        (float*)pq, MROWS, DMODEL, DMODEL);
    gemm_bf16x3_kernel<<<ggrid, 256, GEMM_SMEM>>>(
        (const __nv_bfloat16*)xhi, (const __nv_bfloat16*)xlo,
        (const __nv_bfloat16*)wkhi, (const __nv_bfloat16*)wklo,
        (float*)pk, MROWS, DMODEL, DMODEL);
    gemm_bf16x3_kernel<<<ggrid, 256, GEMM_SMEM>>>(
        (const __nv_bfloat16*)xhi, (const __nv_bfloat16*)xlo,
        (const __nv_bfloat16*)wvhi, (const __nv_bfloat16*)wvlo,
        (float*)pv, MROWS, DMODEL, DMODEL);

    dim3 fgrid(SEQ / BQ, NHEAD, BATCH);
    flash_attn_kernel<<<fgrid, 256, FLASH_SMEM_BYTES>>>(
        (const float*)pq, (const float*)pk, (const float*)pv, (float*)pa);

    split_kernel<<<(nx4 + 255) / 256, 256>>>((const float*)pa,
        (__nv_bfloat16*)aohi, (__nv_bfloat16*)aolo, nx4);
    gemm_bf16x3_kernel<<<ggrid, 256, GEMM_SMEM>>>(
        (const __nv_bfloat16*)aohi, (const __nv_bfloat16*)aolo,
        (const __nv_bfloat16*)wphi, (const __nv_bfloat16*)wplo,
        out, MROWS, DMODEL, DMODEL);
}

// round 5
// speedup vs baseline: 2.8381x; 1.4942x over previous
#include <cuda_runtime.h>
#include <cuda_bf16.h>
#include <stdint.h>
#include <math.h>

// Problem constants (fixed): B=2, S=2048, D=2048, H=16
#define BATCH  2
#define SEQ    2048
#define DMODEL 2048
#define NHEAD  16
#define HDIM   128
#define MROWS  (BATCH * SEQ)   // 4096

// ================= scratch (device globals: allocation-free) =================
__device__ float g_q [(size_t)MROWS * DMODEL];
__device__ float g_k [(size_t)MROWS * DMODEL];
__device__ float g_v [(size_t)MROWS * DMODEL];
__device__ float g_ao[(size_t)MROWS * DMODEL];

__device__ __nv_bfloat16 g_xhi [(size_t)MROWS * DMODEL];
__device__ __nv_bfloat16 g_xlo [(size_t)MROWS * DMODEL];
__device__ __nv_bfloat16 g_aohi[(size_t)MROWS * DMODEL];
__device__ __nv_bfloat16 g_aolo[(size_t)MROWS * DMODEL];
__device__ __nv_bfloat16 g_wqhi[(size_t)DMODEL * DMODEL];
__device__ __nv_bfloat16 g_wqlo[(size_t)DMODEL * DMODEL];
__device__ __nv_bfloat16 g_wkhi[(size_t)DMODEL * DMODEL];
__device__ __nv_bfloat16 g_wklo[(size_t)DMODEL * DMODEL];
__device__ __nv_bfloat16 g_wvhi[(size_t)DMODEL * DMODEL];
__device__ __nv_bfloat16 g_wvlo[(size_t)DMODEL * DMODEL];
__device__ __nv_bfloat16 g_wphi[(size_t)DMODEL * DMODEL];
__device__ __nv_bfloat16 g_wplo[(size_t)DMODEL * DMODEL];

// ================= PTX helpers (baseline features only) ======
__device__ __forceinline__ uint32_t smem_u32(const void* p) {
    uint32_t a;
    asm("{ .reg .u64 t; cvta.to.shared.u64 t, %1; cvt.u32.u64 %0, t; }" : "=r"(a) : "l"(p));
    return a;
}
__device__ __forceinline__ void cp_async16(uint32_t dst, const void* src) {
    asm volatile("cp.async.cg.shared.global [%0], [%1], 16;" :: "r"(dst), "l"(src) : "memory");
}
__device__ __forceinline__ void cp_commit() {
    asm volatile("cp.async.commit_group;" ::: "memory");
}
__device__ __forceinline__ void cp_wait1() {
    asm volatile("cp.async.wait_group 1;" ::: "memory");
}
__device__ __forceinline__ void cp_wait0() {
    asm volatile("cp.async.wait_group 0;" ::: "memory");
}
__device__ __forceinline__ void ldm_x4(uint32_t& r0, uint32_t& r1, uint32_t& r2, uint32_t& r3,
                                       uint32_t addr) {
    asm volatile("ldmatrix.sync.aligned.m8n8.x4.shared.b16 {%0,%1,%2,%3}, [%4];"
                 : "=r"(r0), "=r"(r1), "=r"(r2), "=r"(r3) : "r"(addr));
}
__device__ __forceinline__ void ldm_x4_t(uint32_t& r0, uint32_t& r1, uint32_t& r2, uint32_t& r3,
                                         uint32_t addr) {
    asm volatile("ldmatrix.sync.aligned.m8n8.x4.trans.shared.b16 {%0,%1,%2,%3}, [%4];"
                 : "=r"(r0), "=r"(r1), "=r"(r2), "=r"(r3) : "r"(addr));
}
__device__ __forceinline__ void mma_bf16(float* c, const uint32_t* a, const uint32_t* b) {
    asm volatile("mma.sync.aligned.m16n8k16.row.col.f32.bf16.bf16.f32 "
                 "{%0,%1,%2,%3}, {%4,%5,%6,%7}, {%8,%9}, {%0,%1,%2,%3};"
                 : "+f"(c[0]), "+f"(c[1]), "+f"(c[2]), "+f"(c[3])
                 : "r"(a[0]), "r"(a[1]), "r"(a[2]), "r"(a[3]), "r"(b[0]), "r"(b[1]));
}
__device__ __forceinline__ void mma_bf16_2(float* c, const uint32_t* a, uint32_t b0, uint32_t b1) {
    asm volatile("mma.sync.aligned.m16n8k16.row.col.f32.bf16.bf16.f32 "
                 "{%0,%1,%2,%3}, {%4,%5,%6,%7}, {%8,%9}, {%0,%1,%2,%3};"
                 : "+f"(c[0]), "+f"(c[1]), "+f"(c[2]), "+f"(c[3])
                 : "r"(a[0]), "r"(a[1]), "r"(a[2]), "r"(a[3]), "r"(b0), "r"(b1));
}
// pack two fp32 into bf16x2: low half = f0, high half = f1
__device__ __forceinline__ uint32_t pack_bf16x2(float f0, float f1) {
    uint32_t r;
    asm("cvt.rn.bf16x2.f32 %0, %1, %2;" : "=r"(r) : "f"(f1), "f"(f0));
    return r;
}
__device__ __forceinline__ float bf16rt(float x) {
    return __bfloat162float(__float2bfloat16(x));
}

// ================= split kernel: fp32 -> (hi, lo) bf16 =================
__global__ __launch_bounds__(256) void split_kernel(
    const float* __restrict__ src, __nv_bfloat16* __restrict__ hi,
    __nv_bfloat16* __restrict__ lo, int n4)
{
    int i = blockIdx.x * blockDim.x + threadIdx.x;
    if (i >= n4) return;
    float4 v = ((const float4*)src)[i];
    __nv_bfloat16 h0 = __float2bfloat16(v.x), h1 = __float2bfloat16(v.y);
    __nv_bfloat16 h2 = __float2bfloat16(v.z), h3 = __float2bfloat16(v.w);
    __nv_bfloat16 l0 = __float2bfloat16(v.x - __bfloat162float(h0));
    __nv_bfloat16 l1 = __float2bfloat16(v.y - __bfloat162float(h1));
    __nv_bfloat16 l2 = __float2bfloat16(v.z - __bfloat162float(h2));
    __nv_bfloat16 l3 = __float2bfloat16(v.w - __bfloat162float(h3));
    __nv_bfloat162* hp = (__nv_bfloat162*)hi;
    __nv_bfloat162* lp = (__nv_bfloat162*)lo;
    hp[i * 2 + 0] = __nv_bfloat162(h0, h1);
    hp[i * 2 + 1] = __nv_bfloat162(h2, h3);
    lp[i * 2 + 0] = __nv_bfloat162(l0, l1);
    lp[i * 2 + 1] = __nv_bfloat162(l2, l3);
}

// ================= mma.sync GEMM: C[M,N] = A[M,K] @ B[N,K]^T ==================
// (unchanged from passing round-4 kernel)
#define GBK        64
#define TILE_B     (128 * 128)
#define STAGE_B    (4 * TILE_B)
#define GEMM_SMEM  (2 * STAGE_B)

#define T_AHI 0
#define T_ALO (1 * TILE_B)
#define T_BHI (2 * TILE_B)
#define T_BLO (3 * TILE_B)

__global__ __launch_bounds__(256) void gemm_bf16x3_kernel(
    const __nv_bfloat16* __restrict__ Ahi, const __nv_bfloat16* __restrict__ Alo,
    const __nv_bfloat16* __restrict__ Bhi, const __nv_bfloat16* __restrict__ Blo,
    float* __restrict__ C, int M, int N, int K)
{
    extern __shared__ char smem[];
    const uint32_t sb = smem_u32(smem);
    const int tid = threadIdx.x;
    const int wid = tid >> 5;
    const int l   = tid & 31;
    const int wm  = wid & 3;
    const int wn  = wid >> 2;
    const int m0  = blockIdx.y * 128;
    const int n0  = blockIdx.x * 128;

    int lrow[4], ldst[4];
    #pragma unroll
    for (int i = 0; i < 4; i++) {
        int idx = tid + i * 256;
        int row = idx >> 3, c16 = idx & 7;
        lrow[i] = row;
        ldst[i] = row * 128 + ((c16 ^ (row & 7)) << 4);
    }

    const __nv_bfloat16* gA[2] = { Ahi, Alo };
    const __nv_bfloat16* gB[2] = { Bhi, Blo };

    auto issue_stage = [&](int c, int buf) {
        uint32_t s0 = sb + buf * STAGE_B;
        #pragma unroll
        for (int i = 0; i < 4; i++) {
            int row = lrow[i];
            int koff = c * GBK + ((tid + i * 256) & 7) * 8;
            cp_async16(s0 + T_AHI + ldst[i], gA[0] + (size_t)(m0 + row) * K + koff);
            cp_async16(s0 + T_ALO + ldst[i], gA[1] + (size_t)(m0 + row) * K + koff);
            cp_async16(s0 + T_BHI + ldst[i], gB[0] + (size_t)(n0 + row) * K + koff);
            cp_async16(s0 + T_BLO + ldst[i], gB[1] + (size_t)(n0 + row) * K + koff);
        }
        cp_commit();
    };

    const int a_rowoff = (l & 15);
    const int a_c16off = (l >> 4);
    const int b_rowoff = (l & 7) | ((l & 16) >> 1);
    const int b_c16off = (l >> 3) & 1;

    float acc[2][8][4];
    #pragma unroll
    for (int mi = 0; mi < 2; mi++)
        #pragma unroll
        for (int nj = 0; nj < 8; nj++)
            #pragma unroll
            for (int t = 0; t < 4; t++) acc[mi][nj][t] = 0.f;

    const int nchunks = K / GBK;
    issue_stage(0, 0);
    issue_stage(1, 1);

    for (int c = 0; c < nchunks; c++) {
        const int buf = c & 1;
        if (c < nchunks - 2) cp_wait1(); else cp_wait0();
        __syncthreads();

        const uint32_t s0 = sb + buf * STAGE_B;
        #pragma unroll
        for (int kk = 0; kk < 4; kk++) {
            uint32_t ahi[2][4], alo[2][4];
            #pragma unroll
            for (int mi = 0; mi < 2; mi++) {
                int row = wm * 32 + mi * 16 + a_rowoff;
                int c16 = kk * 2 + a_c16off;
                uint32_t ad = s0 + row * 128 + ((c16 ^ (row & 7)) << 4);
                ldm_x4(ahi[mi][0], ahi[mi][1], ahi[mi][2], ahi[mi][3], ad + T_AHI);
                ldm_x4(alo[mi][0], alo[mi][1], alo[mi][2], alo[mi][3], ad + T_ALO);
            }
            uint32_t bhi[8][2], blo[8][2];
            #pragma unroll
            for (int p = 0; p < 4; p++) {
                int row = wn * 64 + p * 16 + b_rowoff;
                int c16 = kk * 2 + b_c16off;
                uint32_t ad = s0 + row * 128 + ((c16 ^ (row & 7)) << 4);
                ldm_x4(bhi[2*p][0], bhi[2*p][1], bhi[2*p+1][0], bhi[2*p+1][1], ad + T_BHI);
                ldm_x4(blo[2*p][0], blo[2*p][1], blo[2*p+1][0], blo[2*p+1][1], ad + T_BLO);
            }
            #pragma unroll
            for (int mi = 0; mi < 2; mi++)
                #pragma unroll
                for (int nj = 0; nj < 8; nj++) {
                    mma_bf16(acc[mi][nj], ahi[mi], bhi[nj]);
                    mma_bf16(acc[mi][nj], ahi[mi], blo[nj]);
                    mma_bf16(acc[mi][nj], alo[mi], bhi[nj]);
                }
        }
        __syncthreads();
        if (c + 2 < nchunks) issue_stage(c + 2, buf);
    }

    const int er = l >> 2;
    const int ec = (l & 3) * 2;
    #pragma unroll
    for (int mi = 0; mi < 2; mi++) {
        int grow = m0 + wm * 32 + mi * 16 + er;
        #pragma unroll
        for (int nj = 0; nj < 8; nj++) {
            int gcol = n0 + wn * 64 + nj * 8 + ec;
            *(float2*)&C[(size_t)grow * N + gcol]       = make_float2(acc[mi][nj][0], acc[mi][nj][1]);
            *(float2*)&C[(size_t)(grow + 8) * N + gcol] = make_float2(acc[mi][nj][2], acc[mi][nj][3]);
        }
    }
}

// ============================================================
// Tensor-core flash attention (causal) — bf16x3 QK^T and PV, fp32 softmax.
// Block: 128 threads (4 warps); BQ=64, BKV=64, hd=128.
// Warp w owns q-rows [w*16, w*16+16). Softmax state in registers.
// smem: 6 tiles of 64 rows x 128 bf16 (256B rows, XOR-swizzled 16B chunks).
// ============================================================
#define FT_QHI 0
#define FT_QLO 16384
#define FT_KHI 32768
#define FT_KLO 49152
#define FT_VHI 65536
#define FT_VLO 81920
#define FLASH_TC_SMEM 98304

// swizzled byte offset of (row, 16B-chunk c16) in a 256B-row tile
__device__ __forceinline__ uint32_t fsw(int row, int c16) {
    return (uint32_t)(row * 256 + ((c16 ^ ((row & 7) << 1)) << 4));
}

// load 64x128 fp32 tile -> hi/lo bf16 smem tiles (optionally scaled)
__device__ __forceinline__ void load_tile_hl(const float* __restrict__ src,
                                             char* s_hi, char* s_lo, int tid, float mul)
{
    #pragma unroll
    for (int i = 0; i < 8; i++) {
        int idx = tid + i * 128;
        int row = idx >> 4, c16 = idx & 15;
        const float4* p = (const float4*)(src + (size_t)row * DMODEL + c16 * 8);
        float4 f0 = p[0], f1 = p[1];
        float f[8] = { f0.x * mul, f0.y * mul, f0.z * mul, f0.w * mul,
                       f1.x * mul, f1.y * mul, f1.z * mul, f1.w * mul };
        uint32_t hi[4], lo[4];
        #pragma unroll
        for (int q2 = 0; q2 < 4; q2++) {
            float a = f[2 * q2], b = f[2 * q2 + 1];
            hi[q2] = pack_bf16x2(a, b);
            lo[q2] = pack_bf16x2(a - bf16rt(a), b - bf16rt(b));
        }
        uint32_t off = fsw(row, c16);
        *(uint4*)(s_hi + off) = make_uint4(hi[0], hi[1], hi[2], hi[3]);
        *(uint4*)(s_lo + off) = make_uint4(lo[0], lo[1], lo[2], lo[3]);
    }
}

__global__ __launch_bounds__(128) void flash_attn_tc_kernel(
    const float* __restrict__ q, const float* __restrict__ k,
    const float* __restrict__ v, float* __restrict__ o)
{
    extern __shared__ char fsm[];
    const uint32_t sb = smem_u32(fsm);
    const int tid = threadIdx.x;
    const int wid = tid >> 5;
    const int l   = tid & 31;
    const int qt = blockIdx.x;
    const int h  = blockIdx.y;
    const int b  = blockIdx.z;
    const int q0 = qt * 64;

    const float scale = 0.08838834764831845f;   // 1/sqrt(128)

    // load Q tile (scaled) into Qhi/Qlo
    load_tile_hl(q + ((size_t)b * SEQ + q0) * DMODEL + h * HDIM,
                 fsm + FT_QHI, fsm + FT_QLO, tid, scale);

    const int r  = l >> 2;       // fragment row within m16 (plus +8)
    const int cq = l & 3;        // quad column

    // ldmatrix lane offsets
    const int a_rowoff = (l & 15);
    const int a_c16off = (l >> 4);
    const int b_rowoff = (l & 7) | ((l & 16) >> 1);
    const int b_c16off = (l >> 3) & 1;

    float m0v = -1e30f, m1v = -1e30f, l0v = 0.f, l1v = 0.f;
    float O[16][4];
    #pragma unroll
    for (int g = 0; g < 16; g++)
        #pragma unroll
        for (int t = 0; t < 4; t++) O[g][t] = 0.f;

    for (int kt = 0; kt <= qt; kt++) {
        __syncthreads();   // previous iteration's readers done before overwrite
        const size_t gkv = ((size_t)b * SEQ + kt * 64) * DMODEL + h * HDIM;
        load_tile_hl(k + gkv, fsm + FT_KHI, fsm + FT_KLO, tid, 1.0f);
        load_tile_hl(v + gkv, fsm + FT_VHI, fsm + FT_VLO, tid, 1.0f);
        __syncthreads();

        // ---- scores S = Qs @ K^T (3-term bf16) ----
        float s[8][4];
        #pragma unroll
        for (int nj = 0; nj < 8; nj++)
            #pragma unroll
            for (int t = 0; t < 4; t++) s[nj][t] = 0.f;

        #pragma unroll
        for (int j = 0; j < 8; j++) {          // 8 k16 steps over hd=128
            int arow = wid * 16 + a_rowoff;
            uint32_t aad = sb + fsw(arow, 2 * j + a_c16off);
            uint32_t ah[4], al_[4];
            ldm_x4(ah[0], ah[1], ah[2], ah[3], aad + FT_QHI);
            ldm_x4(al_[0], al_[1], al_[2], al_[3], aad + FT_QLO);

            uint32_t bh[8][2], bl[8][2];
            #pragma unroll
            for (int p = 0; p < 4; p++) {
                int brow = p * 16 + b_rowoff;
                uint32_t bad = sb + fsw(brow, 2 * j + b_c16off);
                ldm_x4(bh[2*p][0], bh[2*p][1], bh[2*p+1][0], bh[2*p+1][1], bad + FT_KHI);
                ldm_x4(bl[2*p][0], bl[2*p][1], bl[2*p+1][0], bl[2*p+1][1], bad + FT_KLO);
            }
            #pragma unroll
            for (int nj = 0; nj < 8; nj++) {
                mma_bf16(s[nj], ah,  bh[nj]);
                mma_bf16(s[nj], ah,  bl[nj]);
                mma_bf16(s[nj], al_, bh[nj]);
            }
        }

        // ---- causal mask (diagonal tile only) ----
        if (kt == qt) {
            #pragma unroll
            for (int nj = 0; nj < 8; nj++)
                #pragma unroll
                for (int t = 0; t < 4; t++) {
                    int coll = nj * 8 + 2 * cq + (t & 1);
                    int rowl = wid * 16 + r + ((t >> 1) << 3);
                    if (coll > rowl) s[nj][t] = -1e30f;
                }
        }

        // ---- online softmax (per-warp rows, quad shuffles) ----
        float mx0 = -1e30f, mx1 = -1e30f;
        #pragma unroll
        for (int nj = 0; nj < 8; nj++) {
            mx0 = fmaxf(mx0, fmaxf(s[nj][0], s[nj][1]));
            mx1 = fmaxf(mx1, fmaxf(s[nj][2], s[nj][3]));
        }
        mx0 = fmaxf(mx0, __shfl_xor_sync(0xffffffffu, mx0, 1));
        mx0 = fmaxf(mx0, __shfl_xor_sync(0xffffffffu, mx0, 2));
        mx1 = fmaxf(mx1, __shfl_xor_sync(0xffffffffu, mx1, 1));
        mx1 = fmaxf(mx1, __shfl_xor_sync(0xffffffffu, mx1, 2));

        float mn0 = fmaxf(m0v, mx0), mn1 = fmaxf(m1v, mx1);
        float al0 = __expf(m0v - mn0), al1 = __expf(m1v - mn1);
        m0v = mn0; m1v = mn1;

        #pragma unroll
        for (int g = 0; g < 16; g++) {
            O[g][0] *= al0; O[g][1] *= al0;
            O[g][2] *= al1; O[g][3] *= al1;
        }

        float rs0 = 0.f, rs1 = 0.f;
        #pragma unroll
        for (int nj = 0; nj < 8; nj++) {
            s[nj][0] = __expf(s[nj][0] - mn0);
            s[nj][1] = __expf(s[nj][1] - mn0);
            s[nj][2] = __expf(s[nj][2] - mn1);
            s[nj][3] = __expf(s[nj][3] - mn1);
            rs0 += s[nj][0] + s[nj][1];
            rs1 += s[nj][2] + s[nj][3];
        }
        rs0 += __shfl_xor_sync(0xffffffffu, rs0, 1);
        rs0 += __shfl_xor_sync(0xffffffffu, rs0, 2);
        rs1 += __shfl_xor_sync(0xffffffffu, rs1, 1);
        rs1 += __shfl_xor_sync(0xffffffffu, rs1, 2);
        l0v = l0v * al0 + rs0;
        l1v = l1v * al1 + rs1;

        // ---- O += P @ V (3-term bf16: Phi*Vhi + Phi*Vlo + Plo*Vhi) ----
        #pragma unroll
        for (int j = 0; j < 4; j++) {          // 4 k16 steps over kv=64
            // repack score frags 2j, 2j+1 into A operand (hi + residual lo)
            uint32_t pah[4], pal[4];
            {
                float p00 = s[2*j][0],   p01 = s[2*j][1];
                float p02 = s[2*j][2],   p03 = s[2*j][3];
                float p10 = s[2*j+1][0], p11 = s[2*j+1][1];
                float p12 = s[2*j+1][2], p13 = s[2*j+1][3];
                pah[0] = pack_bf16x2(p00, p01);
                pah[1] = pack_bf16x2(p02, p03);
                pah[2] = pack_bf16x2(p10, p11);
                pah[3] = pack_bf16x2(p12, p13);
                pal[0] = pack_bf16x2(p00 - bf16rt(p00), p01 - bf16rt(p01));
                pal[1] = pack_bf16x2(p02 - bf16rt(p02), p03 - bf16rt(p03));
                pal[2] = pack_bf16x2(p10 - bf16rt(p10), p11 - bf16rt(p11));
                pal[3] = pack_bf16x2(p12 - bf16rt(p12), p13 - bf16rt(p13));
            }
            #pragma unroll
            for (int g = 0; g < 8; g++) {      // n16 groups over hd=128
                int vrow = j * 16 + (l & 15);
                uint32_t vad = sb + fsw(vrow, 2 * g + (l >> 4));
                uint32_t vh0, vh1, vh2, vh3, vl0, vl1, vl2, vl3;
                ldm_x4_t(vh0, vh1, vh2, vh3, vad + FT_VHI);
                ldm_x4_t(vl0, vl1, vl2, vl3, vad + FT_VLO);
                mma_bf16_2(O[2*g],     pah, vh0, vh1);
                mma_bf16_2(O[2*g],     pah, vl0, vl1);
                mma_bf16_2(O[2*g],     pal, vh0, vh1);
                mma_bf16_2(O[2*g + 1], pah, vh2, vh3);
                mma_bf16_2(O[2*g + 1], pah, vl2, vl3);
                mma_bf16_2(O[2*g + 1], pal, vh2, vh3);
            }
        }
    }

    // ---- epilogue: divide by l, write fp32 ----
    const float i0 = 1.0f / l0v;
    const float i1 = 1.0f / l1v;
    const size_t obase = ((size_t)b * SEQ + q0 + wid * 16 + r) * DMODEL + h * HDIM;
    #pragma unroll
    for (int g = 0; g < 16; g++) {
        int col = g * 8 + 2 * cq;
        *(float2*)&o[obase + col] = make_float2(O[g][0] * i0, O[g][1] * i0);
        *(float2*)&o[obase + (size_t)8 * DMODEL + col] = make_float2(O[g][2] * i1, O[g][3] * i1);
    }
}

// ============================================================
// launcher
// ============================================================
extern "C" void kernel_launch(void* const* d_in, const int* in_sizes, int n_in,
                              void* d_out, int out_size)
{
    const float* x  = (const float*)d_in[0];
    const float* Wq = (const float*)d_in[1];
    const float* Wk = (const float*)d_in[2];
    const float* Wv = (const float*)d_in[3];
    const float* Wp = (const float*)d_in[4];
    float* out = (float*)d_out;

    void *pq, *pk, *pv, *pa;
    cudaGetSymbolAddress(&pq, g_q);
    cudaGetSymbolAddress(&pk, g_k);
    cudaGetSymbolAddress(&pv, g_v);
    cudaGetSymbolAddress(&pa, g_ao);

    void *xhi, *xlo, *aohi, *aolo;
    void *wqhi, *wqlo, *wkhi, *wklo, *wvhi, *wvlo, *wphi, *wplo;
    cudaGetSymbolAddress(&xhi,  g_xhi);  cudaGetSymbolAddress(&xlo,  g_xlo);
    cudaGetSymbolAddress(&aohi, g_aohi); cudaGetSymbolAddress(&aolo, g_aolo);
    cudaGetSymbolAddress(&wqhi, g_wqhi); cudaGetSymbolAddress(&wqlo, g_wqlo);
    cudaGetSymbolAddress(&wkhi, g_wkhi); cudaGetSymbolAddress(&wklo, g_wklo);
    cudaGetSymbolAddress(&wvhi, g_wvhi); cudaGetSymbolAddress(&wvlo, g_wvlo);
    cudaGetSymbolAddress(&wphi, g_wphi); cudaGetSymbolAddress(&wplo, g_wplo);

    cudaFuncSetAttribute(flash_attn_tc_kernel,
                         cudaFuncAttributeMaxDynamicSharedMemorySize, FLASH_TC_SMEM);
    cudaFuncSetAttribute(gemm_bf16x3_kernel,
                         cudaFuncAttributeMaxDynamicSharedMemorySize, GEMM_SMEM);

    const int nx4 = (MROWS * DMODEL) / 4;
    const int nw4 = (DMODEL * DMODEL) / 4;

    split_kernel<<<(nx4 + 255) / 256, 256>>>(x,  (__nv_bfloat16*)xhi,  (__nv_bfloat16*)xlo,  nx4);
    split_kernel<<<(nw4 + 255) / 256, 256>>>(Wq, (__nv_bfloat16*)wqhi, (__nv_bfloat16*)wqlo, nw4);
    split_kernel<<<(nw4 + 255) / 256, 256>>>(Wk, (__nv_bfloat16*)wkhi, (__nv_bfloat16*)wklo, nw4);
    split_kernel<<<(nw4 + 255) / 256, 256>>>(Wv, (__nv_bfloat16*)wvhi, (__nv_bfloat16*)wvlo, nw4);
    split_kernel<<<(nw4 + 255) / 256, 256>>>(Wp, (__nv_bfloat16*)wphi, (__nv_bfloat16*)wplo, nw4);

    dim3 ggrid(DMODEL / 128, MROWS / 128);   // (16, 32)

    gemm_bf16x3_kernel<<<ggrid, 256, GEMM_SMEM>>>(
        (const __nv_bfloat16*)xhi, (const __nv_bfloat16*)xlo,
        (const __nv_bfloat16*)wqhi, (const __nv_bfloat16*)wqlo,
        (float*)pq, MROWS, DMODEL, DMODEL);
    gemm_bf16x3_kernel<<<ggrid, 256, GEMM_SMEM>>>(
        (const __nv_bfloat16*)xhi, (const __nv_bfloat16*)xlo,
        (const __nv_bfloat16*)wkhi, (const __nv_bfloat16*)wklo,
        (float*)pk, MROWS, DMODEL, DMODEL);
    gemm_bf16x3_kernel<<<ggrid, 256, GEMM_SMEM>>>(
        (const __nv_bfloat16*)xhi, (const __nv_bfloat16*)xlo,
        (const __nv_bfloat16*)wvhi, (const __nv_bfloat16*)wvlo,
        (float*)pv, MROWS, DMODEL, DMODEL);

    dim3 fgrid(SEQ / 64, NHEAD, BATCH);      // (32, 16, 2)
    flash_attn_tc_kernel<<<fgrid, 128, FLASH_TC_SMEM>>>(
        (const float*)pq, (const float*)pk, (const float*)pv, (float*)pa);

    split_kernel<<<(nx4 + 255) / 256, 256>>>((const float*)pa,
        (__nv_bfloat16*)aohi, (__nv_bfloat16*)aolo, nx4);
    gemm_bf16x3_kernel<<<ggrid, 256, GEMM_SMEM>>>(
        (const __nv_bfloat16*)aohi, (const __nv_bfloat16*)aolo,
        (const __nv_bfloat16*)wphi, (const __nv_bfloat16*)wplo,
        out, MROWS, DMODEL, DMODEL);
}

// round 7
// speedup vs baseline: 3.0441x; 1.0726x over previous
#include <cuda_runtime.h>
#include <cuda_bf16.h>
#include <stdint.h>
#include <math.h>

// Problem constants (fixed): B=2, S=2048, D=2048, H=16
#define BATCH  2
#define SEQ    2048
#define DMODEL 2048
#define NHEAD  16
#define HDIM   128
#define MROWS  (BATCH * SEQ)   // 4096

// ================= scratch (device globals: allocation-free) =================
__device__ __nv_bfloat16 g_qhi [(size_t)MROWS * DMODEL];
__device__ __nv_bfloat16 g_qlo [(size_t)MROWS * DMODEL];
__device__ __nv_bfloat16 g_khi [(size_t)MROWS * DMODEL];
__device__ __nv_bfloat16 g_klo [(size_t)MROWS * DMODEL];
__device__ __nv_bfloat16 g_vhi [(size_t)MROWS * DMODEL];
__device__ __nv_bfloat16 g_vlo [(size_t)MROWS * DMODEL];
__device__ __nv_bfloat16 g_aohi[(size_t)MROWS * DMODEL];
__device__ __nv_bfloat16 g_aolo[(size_t)MROWS * DMODEL];

__device__ __nv_bfloat16 g_xhi [(size_t)MROWS * DMODEL];
__device__ __nv_bfloat16 g_xlo [(size_t)MROWS * DMODEL];
__device__ __nv_bfloat16 g_wqhi[(size_t)DMODEL * DMODEL];
__device__ __nv_bfloat16 g_wqlo[(size_t)DMODEL * DMODEL];
__device__ __nv_bfloat16 g_wkhi[(size_t)DMODEL * DMODEL];
__device__ __nv_bfloat16 g_wklo[(size_t)DMODEL * DMODEL];
__device__ __nv_bfloat16 g_wvhi[(size_t)DMODEL * DMODEL];
__device__ __nv_bfloat16 g_wvlo[(size_t)DMODEL * DMODEL];
__device__ __nv_bfloat16 g_wphi[(size_t)DMODEL * DMODEL];
__device__ __nv_bfloat16 g_wplo[(size_t)DMODEL * DMODEL];

// ================= PTX helpers (baseline features only) ======
__device__ __forceinline__ uint32_t smem_u32(const void* p) {
    uint32_t a;
    asm("{ .reg .u64 t; cvta.to.shared.u64 t, %1; cvt.u32.u64 %0, t; }" : "=r"(a) : "l"(p));
    return a;
}
__device__ __forceinline__ void cp_async16(uint32_t dst, const void* src) {
    asm volatile("cp.async.cg.shared.global [%0], [%1], 16;" :: "r"(dst), "l"(src) : "memory");
}
__device__ __forceinline__ void cp_commit() {
    asm volatile("cp.async.commit_group;" ::: "memory");
}
__device__ __forceinline__ void cp_wait1() {
    asm volatile("cp.async.wait_group 1;" ::: "memory");
}
__device__ __forceinline__ void cp_wait0() {
    asm volatile("cp.async.wait_group 0;" ::: "memory");
}
__device__ __forceinline__ void ldm_x4(uint32_t& r0, uint32_t& r1, uint32_t& r2, uint32_t& r3,
                                       uint32_t addr) {
    asm volatile("ldmatrix.sync.aligned.m8n8.x4.shared.b16 {%0,%1,%2,%3}, [%4];"
                 : "=r"(r0), "=r"(r1), "=r"(r2), "=r"(r3) : "r"(addr));
}
__device__ __forceinline__ void ldm_x4_t(uint32_t& r0, uint32_t& r1, uint32_t& r2, uint32_t& r3,
                                         uint32_t addr) {
    asm volatile("ldmatrix.sync.aligned.m8n8.x4.trans.shared.b16 {%0,%1,%2,%3}, [%4];"
                 : "=r"(r0), "=r"(r1), "=r"(r2), "=r"(r3) : "r"(addr));
}
__device__ __forceinline__ void mma_bf16(float* c, const uint32_t* a, const uint32_t* b) {
    asm volatile("mma.sync.aligned.m16n8k16.row.col.f32.bf16.bf16.f32 "
                 "{%0,%1,%2,%3}, {%4,%5,%6,%7}, {%8,%9}, {%0,%1,%2,%3};"
                 : "+f"(c[0]), "+f"(c[1]), "+f"(c[2]), "+f"(c[3])
                 : "r"(a[0]), "r"(a[1]), "r"(a[2]), "r"(a[3]), "r"(b[0]), "r"(b[1]));
}
__device__ __forceinline__ void mma_bf16_2(float* c, const uint32_t* a, uint32_t b0, uint32_t b1) {
    asm volatile("mma.sync.aligned.m16n8k16.row.col.f32.bf16.bf16.f32 "
                 "{%0,%1,%2,%3}, {%4,%5,%6,%7}, {%8,%9}, {%0,%1,%2,%3};"
                 : "+f"(c[0]), "+f"(c[1]), "+f"(c[2]), "+f"(c[3])
                 : "r"(a[0]), "r"(a[1]), "r"(a[2]), "r"(a[3]), "r"(b0), "r"(b1));
}
// pack two fp32 into bf16x2: low half = f0, high half = f1
__device__ __forceinline__ uint32_t pack_bf16x2(float f0, float f1) {
    uint32_t r;
    asm("cvt.rn.bf16x2.f32 %0, %1, %2;" : "=r"(r) : "f"(f1), "f"(f0));
    return r;
}
__device__ __forceinline__ float bf16rt(float x) {
    return __bfloat162float(__float2bfloat16(x));
}

// ================= split kernel: fp32 -> (hi, lo) bf16 =================
__global__ __launch_bounds__(256) void split_kernel(
    const float* __restrict__ src, __nv_bfloat16* __restrict__ hi,
    __nv_bfloat16* __restrict__ lo, int n4)
{
    int i = blockIdx.x * blockDim.x + threadIdx.x;
    if (i >= n4) return;
    float4 v = ((const float4*)src)[i];
    __nv_bfloat16 h0 = __float2bfloat16(v.x), h1 = __float2bfloat16(v.y);
    __nv_bfloat16 h2 = __float2bfloat16(v.z), h3 = __float2bfloat16(v.w);
    __nv_bfloat16 l0 = __float2bfloat16(v.x - __bfloat162float(h0));
    __nv_bfloat16 l1 = __float2bfloat16(v.y - __bfloat162float(h1));
    __nv_bfloat16 l2 = __float2bfloat16(v.z - __bfloat162float(h2));
    __nv_bfloat16 l3 = __float2bfloat16(v.w - __bfloat162float(h3));
    __nv_bfloat162* hp = (__nv_bfloat162*)hi;
    __nv_bfloat162* lp = (__nv_bfloat162*)lo;
    hp[i * 2 + 0] = __nv_bfloat162(h0, h1);
    hp[i * 2 + 1] = __nv_bfloat162(h2, h3);
    lp[i * 2 + 0] = __nv_bfloat162(l0, l1);
    lp[i * 2 + 1] = __nv_bfloat162(l2, l3);
}

// ================= mma.sync GEMM: C[M,N] = A[M,K] @ B[N,K]^T ==================
// bf16x3 split: C = Ahi*Bhi + Ahi*Blo + Alo*Bhi.
// MODE 0: fp32 output to C. MODE 1: (hi, lo) bf16 output, scaled by mul.
#define GBK        64
#define TILE_B     (128 * 128)
#define STAGE_B    (4 * TILE_B)
#define GEMM_SMEM  (2 * STAGE_B)

#define T_AHI 0
#define T_ALO (1 * TILE_B)
#define T_BHI (2 * TILE_B)
#define T_BLO (3 * TILE_B)

template<int MODE>
__global__ __launch_bounds__(256) void gemm_bf16x3_kernel(
    const __nv_bfloat16* __restrict__ Ahi, const __nv_bfloat16* __restrict__ Alo,
    const __nv_bfloat16* __restrict__ Bhi, const __nv_bfloat16* __restrict__ Blo,
    float* __restrict__ C, __nv_bfloat16* __restrict__ Chi,
    __nv_bfloat16* __restrict__ Clo, float mul, int M, int N, int K)
{
    extern __shared__ char smem[];
    const uint32_t sb = smem_u32(smem);
    const int tid = threadIdx.x;
    const int wid = tid >> 5;
    const int l   = tid & 31;
    const int wm  = wid & 3;
    const int wn  = wid >> 2;
    const int m0  = blockIdx.y * 128;
    const int n0  = blockIdx.x * 128;

    int lrow[4], ldst[4];
    #pragma unroll
    for (int i = 0; i < 4; i++) {
        int idx = tid + i * 256;
        int row = idx >> 3, c16 = idx & 7;
        lrow[i] = row;
        ldst[i] = row * 128 + ((c16 ^ (row & 7)) << 4);
    }

    const __nv_bfloat16* gA[2] = { Ahi, Alo };
    const __nv_bfloat16* gB[2] = { Bhi, Blo };

    auto issue_stage = [&](int c, int buf) {
        uint32_t s0 = sb + buf * STAGE_B;
        #pragma unroll
        for (int i = 0; i < 4; i++) {
            int row = lrow[i];
            int koff = c * GBK + ((tid + i * 256) & 7) * 8;
            cp_async16(s0 + T_AHI + ldst[i], gA[0] + (size_t)(m0 + row) * K + koff);
            cp_async16(s0 + T_ALO + ldst[i], gA[1] + (size_t)(m0 + row) * K + koff);
            cp_async16(s0 + T_BHI + ldst[i], gB[0] + (size_t)(n0 + row) * K + koff);
            cp_async16(s0 + T_BLO + ldst[i], gB[1] + (size_t)(n0 + row) * K + koff);
        }
        cp_commit();
    };

    const int a_rowoff = (l & 15);
    const int a_c16off = (l >> 4);
    const int b_rowoff = (l & 7) | ((l & 16) >> 1);
    const int b_c16off = (l >> 3) & 1;

    float acc[2][8][4];
    #pragma unroll
    for (int mi = 0; mi < 2; mi++)
        #pragma unroll
        for (int nj = 0; nj < 8; nj++)
            #pragma unroll
            for (int t = 0; t < 4; t++) acc[mi][nj][t] = 0.f;

    const int nchunks = K / GBK;
    issue_stage(0, 0);
    issue_stage(1, 1);

    for (int c = 0; c < nchunks; c++) {
        const int buf = c & 1;
        if (c < nchunks - 2) cp_wait1(); else cp_wait0();
        __syncthreads();

        const uint32_t s0 = sb + buf * STAGE_B;
        #pragma unroll
        for (int kk = 0; kk < 4; kk++) {
            uint32_t ahi[2][4], alo[2][4];
            #pragma unroll
            for (int mi = 0; mi < 2; mi++) {
                int row = wm * 32 + mi * 16 + a_rowoff;
                int c16 = kk * 2 + a_c16off;
                uint32_t ad = s0 + row * 128 + ((c16 ^ (row & 7)) << 4);
                ldm_x4(ahi[mi][0], ahi[mi][1], ahi[mi][2], ahi[mi][3], ad + T_AHI);
                ldm_x4(alo[mi][0], alo[mi][1], alo[mi][2], alo[mi][3], ad + T_ALO);
            }
            uint32_t bhi[8][2], blo[8][2];
            #pragma unroll
            for (int p = 0; p < 4; p++) {
                int row = wn * 64 + p * 16 + b_rowoff;
                int c16 = kk * 2 + b_c16off;
                uint32_t ad = s0 + row * 128 + ((c16 ^ (row & 7)) << 4);
                ldm_x4(bhi[2*p][0], bhi[2*p][1], bhi[2*p+1][0], bhi[2*p+1][1], ad + T_BHI);
                ldm_x4(blo[2*p][0], blo[2*p][1], blo[2*p+1][0], blo[2*p+1][1], ad + T_BLO);
            }
            #pragma unroll
            for (int mi = 0; mi < 2; mi++)
                #pragma unroll
                for (int nj = 0; nj < 8; nj++) {
                    mma_bf16(acc[mi][nj], ahi[mi], bhi[nj]);
                    mma_bf16(acc[mi][nj], ahi[mi], blo[nj]);
                    mma_bf16(acc[mi][nj], alo[mi], bhi[nj]);
                }
        }
        __syncthreads();
        if (c + 2 < nchunks) issue_stage(c + 2, buf);
    }

    const int er = l >> 2;
    const int ec = (l & 3) * 2;
    #pragma unroll
    for (int mi = 0; mi < 2; mi++) {
        int grow = m0 + wm * 32 + mi * 16 + er;
        #pragma unroll
        for (int nj = 0; nj < 8; nj++) {
            int gcol = n0 + wn * 64 + nj * 8 + ec;
            if (MODE == 0) {
                *(float2*)&C[(size_t)grow * N + gcol] =
                    make_float2(acc[mi][nj][0], acc[mi][nj][1]);
                *(float2*)&C[(size_t)(grow + 8) * N + gcol] =
                    make_float2(acc[mi][nj][2], acc[mi][nj][3]);
            } else {
                float c0 = acc[mi][nj][0] * mul, c1 = acc[mi][nj][1] * mul;
                float c2 = acc[mi][nj][2] * mul, c3 = acc[mi][nj][3] * mul;
                *(uint32_t*)&Chi[(size_t)grow * N + gcol]       = pack_bf16x2(c0, c1);
                *(uint32_t*)&Clo[(size_t)grow * N + gcol]       =
                    pack_bf16x2(c0 - bf16rt(c0), c1 - bf16rt(c1));
                *(uint32_t*)&Chi[(size_t)(grow + 8) * N + gcol] = pack_bf16x2(c2, c3);
                *(uint32_t*)&Clo[(size_t)(grow + 8) * N + gcol] =
                    pack_bf16x2(c2 - bf16rt(c2), c3 - bf16rt(c3));
            }
        }
    }
}

// ============================================================
// Tensor-core flash attention (causal) — inputs pre-split bf16 hi/lo.
// Block: 128 threads (4 warps); BQ=64, BKV=64, hd=128.
// smem: 6 tiles of 64 rows x 128 bf16 (256B rows, XOR-swizzled), 96 KB.
// ============================================================
#define FT_QHI 0
#define FT_QLO 16384
#define FT_KHI 32768
#define FT_KLO 49152
#define FT_VHI 65536
#define FT_VLO 81920
#define FLASH_TC_SMEM 98304

__device__ __forceinline__ uint32_t fsw(int row, int c16) {
    return (uint32_t)(row * 256 + ((c16 ^ ((row & 7) << 1)) << 4));
}

__global__ __launch_bounds__(128) void flash_attn_tc_kernel(
    const __nv_bfloat16* __restrict__ qhi, const __nv_bfloat16* __restrict__ qlo,
    const __nv_bfloat16* __restrict__ khi, const __nv_bfloat16* __restrict__ klo,
    const __nv_bfloat16* __restrict__ vhi, const __nv_bfloat16* __restrict__ vlo,
    __nv_bfloat16* __restrict__ ohi, __nv_bfloat16* __restrict__ olo)
{
    extern __shared__ char fsm[];
    const uint32_t sb = smem_u32(fsm);
    const int tid = threadIdx.x;
    const int wid = tid >> 5;
    const int l   = tid & 31;
    const int qt = blockIdx.x;
    const int h  = blockIdx.y;
    const int b  = blockIdx.z;
    const int q0 = qt * 64;

    // thread's cp.async slots: 8 chunks per 64x128 tile
    const size_t gq = ((size_t)b * SEQ + q0) * DMODEL + h * HDIM;
    #pragma unroll
    for (int i = 0; i < 8; i++) {
        int idx = tid + i * 128;
        int row = idx >> 4, c16 = idx & 15;
        uint32_t off = fsw(row, c16);
        size_t src = gq + (size_t)row * DMODEL + c16 * 8;
        cp_async16(sb + FT_QHI + off, qhi + src);
        cp_async16(sb + FT_QLO + off, qlo + src);
    }
    cp_commit();

    const int r  = l >> 2;
    const int cq = l & 3;

    const int a_rowoff = (l & 15);
    const int a_c16off = (l >> 4);
    const int b_rowoff = (l & 7) | ((l & 16) >> 1);
    const int b_c16off = (l >> 3) & 1;

    float m0v = -1e30f, m1v = -1e30f, l0v = 0.f, l1v = 0.f;
    float O[16][4];
    #pragma unroll
    for (int g = 0; g < 16; g++)
        #pragma unroll
        for (int t = 0; t < 4; t++) O[g][t] = 0.f;

    for (int kt = 0; kt <= qt; kt++) {
        __syncthreads();   // previous iteration's readers done before overwrite
        const size_t gkv = ((size_t)b * SEQ + kt * 64) * DMODEL + h * HDIM;
        #pragma unroll
        for (int i = 0; i < 8; i++) {
            int idx = tid + i * 128;
            int row = idx >> 4, c16 = idx & 15;
            uint32_t off = fsw(row, c16);
            size_t src = gkv + (size_t)row * DMODEL + c16 * 8;
            cp_async16(sb + FT_KHI + off, khi + src);
            cp_async16(sb + FT_KLO + off, klo + src);
            cp_async16(sb + FT_VHI + off, vhi + src);
            cp_async16(sb + FT_VLO + off, vlo + src);
        }
        cp_commit();
        cp_wait0();
        __syncthreads();

        // ---- scores S = Qs @ K^T (3-term bf16) ----
        float s[8][4];
        #pragma unroll
        for (int nj = 0; nj < 8; nj++)
            #pragma unroll
            for (int t = 0; t < 4; t++) s[nj][t] = 0.f;

        #pragma unroll
        for (int j = 0; j < 8; j++) {
            int arow = wid * 16 + a_rowoff;
            uint32_t aad = sb + fsw(arow, 2 * j + a_c16off);
            uint32_t ah[4], al_[4];
            ldm_x4(ah[0], ah[1], ah[2], ah[3], aad + FT_QHI);
            ldm_x4(al_[0], al_[1], al_[2], al_[3], aad + FT_QLO);

            uint32_t bh[8][2], bl[8][2];
            #pragma unroll
            for (int p = 0; p < 4; p++) {
                int brow = p * 16 + b_rowoff;
                uint32_t bad = sb + fsw(brow, 2 * j + b_c16off);
                ldm_x4(bh[2*p][0], bh[2*p][1], bh[2*p+1][0], bh[2*p+1][1], bad + FT_KHI);
                ldm_x4(bl[2*p][0], bl[2*p][1], bl[2*p+1][0], bl[2*p+1][1], bad + FT_KLO);
            }
            #pragma unroll
            for (int nj = 0; nj < 8; nj++) {
                mma_bf16(s[nj], ah,  bh[nj]);
                mma_bf16(s[nj], ah,  bl[nj]);
                mma_bf16(s[nj], al_, bh[nj]);
            }
        }

        // ---- causal mask (diagonal tile only) ----
        if (kt == qt) {
            #pragma unroll
            for (int nj = 0; nj < 8; nj++)
                #pragma unroll
                for (int t = 0; t < 4; t++) {
                    int coll = nj * 8 + 2 * cq + (t & 1);
                    int rowl = wid * 16 + r + ((t >> 1) << 3);
                    if (coll > rowl) s[nj][t] = -1e30f;
                }
        }

        // ---- online softmax ----
        float mx0 = -1e30f, mx1 = -1e30f;
        #pragma unroll
        for (int nj = 0; nj < 8; nj++) {
            mx0 = fmaxf(mx0, fmaxf(s[nj][0], s[nj][1]));
            mx1 = fmaxf(mx1, fmaxf(s[nj][2], s[nj][3]));
        }
        mx0 = fmaxf(mx0, __shfl_xor_sync(0xffffffffu, mx0, 1));
        mx0 = fmaxf(mx0, __shfl_xor_sync(0xffffffffu, mx0, 2));
        mx1 = fmaxf(mx1, __shfl_xor_sync(0xffffffffu, mx1, 1));
        mx1 = fmaxf(mx1, __shfl_xor_sync(0xffffffffu, mx1, 2));

        float mn0 = fmaxf(m0v, mx0), mn1 = fmaxf(m1v, mx1);
        float al0 = __expf(m0v - mn0), al1 = __expf(m1v - mn1);
        m0v = mn0; m1v = mn1;

        #pragma unroll
        for (int g = 0; g < 16; g++) {
            O[g][0] *= al0; O[g][1] *= al0;
            O[g][2] *= al1; O[g][3] *= al1;
        }

        float rs0 = 0.f, rs1 = 0.f;
        #pragma unroll
        for (int nj = 0; nj < 8; nj++) {
            s[nj][0] = __expf(s[nj][0] - mn0);
            s[nj][1] = __expf(s[nj][1] - mn0);
            s[nj][2] = __expf(s[nj][2] - mn1);
            s[nj][3] = __expf(s[nj][3] - mn1);
            rs0 += s[nj][0] + s[nj][1];
            rs1 += s[nj][2] + s[nj][3];
        }
        rs0 += __shfl_xor_sync(0xffffffffu, rs0, 1);
        rs0 += __shfl_xor_sync(0xffffffffu, rs0, 2);
        rs1 += __shfl_xor_sync(0xffffffffu, rs1, 1);
        rs1 += __shfl_xor_sync(0xffffffffu, rs1, 2);
        l0v = l0v * al0 + rs0;
        l1v = l1v * al1 + rs1;

        // ---- O += P @ V (3-term bf16) ----
        #pragma unroll
        for (int j = 0; j < 4; j++) {
            uint32_t pah[4], pal[4];
            {
                float p00 = s[2*j][0],   p01 = s[2*j][1];
                float p02 = s[2*j][2],   p03 = s[2*j][3];
                float p10 = s[2*j+1][0], p11 = s[2*j+1][1];
                float p12 = s[2*j+1][2], p13 = s[2*j+1][3];
                pah[0] = pack_bf16x2(p00, p01);
                pah[1] = pack_bf16x2(p02, p03);
                pah[2] = pack_bf16x2(p10, p11);
                pah[3] = pack_bf16x2(p12, p13);
                pal[0] = pack_bf16x2(p00 - bf16rt(p00), p01 - bf16rt(p01));
                pal[1] = pack_bf16x2(p02 - bf16rt(p02), p03 - bf16rt(p03));
                pal[2] = pack_bf16x2(p10 - bf16rt(p10), p11 - bf16rt(p11));
                pal[3] = pack_bf16x2(p12 - bf16rt(p12), p13 - bf16rt(p13));
            }
            #pragma unroll
            for (int g = 0; g < 8; g++) {
                int vrow = j * 16 + (l & 15);
                uint32_t vad = sb + fsw(vrow, 2 * g + (l >> 4));
                uint32_t vh0, vh1, vh2, vh3, vl0, vl1, vl2, vl3;
                ldm_x4_t(vh0, vh1, vh2, vh3, vad + FT_VHI);
                ldm_x4_t(vl0, vl1, vl2, vl3, vad + FT_VLO);
                mma_bf16_2(O[2*g],     pah, vh0, vh1);
                mma_bf16_2(O[2*g],     pah, vl0, vl1);
                mma_bf16_2(O[2*g],     pal, vh0, vh1);
                mma_bf16_2(O[2*g + 1], pah, vh2, vh3);
                mma_bf16_2(O[2*g + 1], pah, vl2, vl3);
                mma_bf16_2(O[2*g + 1], pal, vh2, vh3);
            }
        }
    }

    // ---- epilogue: divide by l, write hi/lo bf16 ----
    const float i0 = 1.0f / l0v;
    const float i1 = 1.0f / l1v;
    const size_t obase = ((size_t)b * SEQ + q0 + wid * 16 + r) * DMODEL + h * HDIM;
    #pragma unroll
    for (int g = 0; g < 16; g++) {
        int col = g * 8 + 2 * cq;
        float a0 = O[g][0] * i0, a1 = O[g][1] * i0;
        float a2 = O[g][2] * i1, a3 = O[g][3] * i1;
        *(uint32_t*)&ohi[obase + col] = pack_bf16x2(a0, a1);
        *(uint32_t*)&olo[obase + col] = pack_bf16x2(a0 - bf16rt(a0), a1 - bf16rt(a1));
        *(uint32_t*)&ohi[obase + (size_t)8 * DMODEL + col] = pack_bf16x2(a2, a3);
        *(uint32_t*)&olo[obase + (size_t)8 * DMODEL + col] =
            pack_bf16x2(a2 - bf16rt(a2), a3 - bf16rt(a3));
    }
}

// ============================================================
// launcher
// ============================================================
extern "C" void kernel_launch(void* const* d_in, const int* in_sizes, int n_in,
                              void* d_out, int out_size)
{
    const float* x  = (const float*)d_in[0];
    const float* Wq = (const float*)d_in[1];
    const float* Wk = (const float*)d_in[2];
    const float* Wv = (const float*)d_in[3];
    const float* Wp = (const float*)d_in[4];
    float* out = (float*)d_out;

    void *qhi, *qlo, *khi, *klo, *vhi, *vlo, *aohi, *aolo;
    cudaGetSymbolAddress(&qhi,  g_qhi);  cudaGetSymbolAddress(&qlo,  g_qlo);
    cudaGetSymbolAddress(&khi,  g_khi);  cudaGetSymbolAddress(&klo,  g_klo);
    cudaGetSymbolAddress(&vhi,  g_vhi);  cudaGetSymbolAddress(&vlo,  g_vlo);
    cudaGetSymbolAddress(&aohi, g_aohi); cudaGetSymbolAddress(&aolo, g_aolo);

    void *xhi, *xlo;
    void *wqhi, *wqlo, *wkhi, *wklo, *wvhi, *wvlo, *wphi, *wplo;
    cudaGetSymbolAddress(&xhi,  g_xhi);  cudaGetSymbolAddress(&xlo,  g_xlo);
    cudaGetSymbolAddress(&wqhi, g_wqhi); cudaGetSymbolAddress(&wqlo, g_wqlo);
    cudaGetSymbolAddress(&wkhi, g_wkhi); cudaGetSymbolAddress(&wklo, g_wklo);
    cudaGetSymbolAddress(&wvhi, g_wvhi); cudaGetSymbolAddress(&wvlo, g_wvlo);
    cudaGetSymbolAddress(&wphi, g_wphi); cudaGetSymbolAddress(&wplo, g_wplo);

    cudaFuncSetAttribute(flash_attn_tc_kernel,
                         cudaFuncAttributeMaxDynamicSharedMemorySize, FLASH_TC_SMEM);
    cudaFuncSetAttribute(gemm_bf16x3_kernel<0>,
                         cudaFuncAttributeMaxDynamicSharedMemorySize, GEMM_SMEM);
    cudaFuncSetAttribute(gemm_bf16x3_kernel<1>,
                         cudaFuncAttributeMaxDynamicSharedMemorySize, GEMM_SMEM);

    const int nx4 = (MROWS * DMODEL) / 4;
    const int nw4 = (DMODEL * DMODEL) / 4;

    split_kernel<<<(nx4 + 255) / 256, 256>>>(x,  (__nv_bfloat16*)xhi,  (__nv_bfloat16*)xlo,  nx4);
    split_kernel<<<(nw4 + 255) / 256, 256>>>(Wq, (__nv_bfloat16*)wqhi, (__nv_bfloat16*)wqlo, nw4);
    split_kernel<<<(nw4 + 255) / 256, 256>>>(Wk, (__nv_bfloat16*)wkhi, (__nv_bfloat16*)wklo, nw4);
    split_kernel<<<(nw4 + 255) / 256, 256>>>(Wv, (__nv_bfloat16*)wvhi, (__nv_bfloat16*)wvlo, nw4);
    split_kernel<<<(nw4 + 255) / 256, 256>>>(Wp, (__nv_bfloat16*)wphi, (__nv_bfloat16*)wplo, nw4);

    dim3 ggrid(DMODEL / 128, MROWS / 128);   // (16, 32)
    const float scale = 0.08838834764831845f;  // 1/sqrt(128), folded into Q

    gemm_bf16x3_kernel<1><<<ggrid, 256, GEMM_SMEM>>>(
        (const __nv_bfloat16*)xhi, (const __nv_bfloat16*)xlo,
        (const __nv_bfloat16*)wqhi, (const __nv_bfloat16*)wqlo,
        nullptr, (__nv_bfloat16*)qhi, (__nv_bfloat16*)qlo, scale, MROWS, DMODEL, DMODEL);
    gemm_bf16x3_kernel<1><<<ggrid, 256, GEMM_SMEM>>>(
        (const __nv_bfloat16*)xhi, (const __nv_bfloat16*)xlo,
        (const __nv_bfloat16*)wkhi, (const __nv_bfloat16*)wklo,
        nullptr, (__nv_bfloat16*)khi, (__nv_bfloat16*)klo, 1.0f, MROWS, DMODEL, DMODEL);
    gemm_bf16x3_kernel<1><<<ggrid, 256, GEMM_SMEM>>>(
        (const __nv_bfloat16*)xhi, (const __nv_bfloat16*)xlo,
        (const __nv_bfloat16*)wvhi, (const __nv_bfloat16*)wvlo,
        nullptr, (__nv_bfloat16*)vhi, (__nv_bfloat16*)vlo, 1.0f, MROWS, DMODEL, DMODEL);

    dim3 fgrid(SEQ / 64, NHEAD, BATCH);      // (32, 16, 2)
    flash_attn_tc_kernel<<<fgrid, 128, FLASH_TC_SMEM>>>(
        (const __nv_bfloat16*)qhi, (const __nv_bfloat16*)qlo,
        (const __nv_bfloat16*)khi, (const __nv_bfloat16*)klo,
        (const __nv_bfloat16*)vhi, (const __nv_bfloat16*)vlo,
        (__nv_bfloat16*)aohi, (__nv_bfloat16*)aolo);

    gemm_bf16x3_kernel<0><<<ggrid, 256, GEMM_SMEM>>>(
        (const __nv_bfloat16*)aohi, (const __nv_bfloat16*)aolo,
        (const __nv_bfloat16*)wphi, (const __nv_bfloat16*)wplo,
        out, nullptr, nullptr, 1.0f, MROWS, DMODEL, DMODEL);
}

// round 8
// speedup vs baseline: 3.1157x; 1.0235x over previous
#include <cuda_runtime.h>
#include <cuda_bf16.h>
#include <stdint.h>
#include <math.h>

// Problem constants (fixed): B=2, S=2048, D=2048, H=16
#define BATCH  2
#define SEQ    2048
#define DMODEL 2048
#define NHEAD  16
#define HDIM   128
#define MROWS  (BATCH * SEQ)   // 4096

// ================= scratch (device globals: allocation-free) =================
__device__ __nv_bfloat16 g_qhi [(size_t)MROWS * DMODEL];
__device__ __nv_bfloat16 g_qlo [(size_t)MROWS * DMODEL];
__device__ __nv_bfloat16 g_khi [(size_t)MROWS * DMODEL];
__device__ __nv_bfloat16 g_klo [(size_t)MROWS * DMODEL];
__device__ __nv_bfloat16 g_vhi [(size_t)MROWS * DMODEL];
__device__ __nv_bfloat16 g_vlo [(size_t)MROWS * DMODEL];
__device__ __nv_bfloat16 g_aohi[(size_t)MROWS * DMODEL];
__device__ __nv_bfloat16 g_aolo[(size_t)MROWS * DMODEL];

__device__ __nv_bfloat16 g_xhi [(size_t)MROWS * DMODEL];
__device__ __nv_bfloat16 g_xlo [(size_t)MROWS * DMODEL];
__device__ __nv_bfloat16 g_wqhi[(size_t)DMODEL * DMODEL];
__device__ __nv_bfloat16 g_wqlo[(size_t)DMODEL * DMODEL];
__device__ __nv_bfloat16 g_wkhi[(size_t)DMODEL * DMODEL];
__device__ __nv_bfloat16 g_wklo[(size_t)DMODEL * DMODEL];
__device__ __nv_bfloat16 g_wvhi[(size_t)DMODEL * DMODEL];
__device__ __nv_bfloat16 g_wvlo[(size_t)DMODEL * DMODEL];
__device__ __nv_bfloat16 g_wphi[(size_t)DMODEL * DMODEL];
__device__ __nv_bfloat16 g_wplo[(size_t)DMODEL * DMODEL];

// ================= PTX helpers (baseline features only) ======
__device__ __forceinline__ uint32_t smem_u32(const void* p) {
    uint32_t a;
    asm("{ .reg .u64 t; cvta.to.shared.u64 t, %1; cvt.u32.u64 %0, t; }" : "=r"(a) : "l"(p));
    return a;
}
__device__ __forceinline__ void cp_async16(uint32_t dst, const void* src) {
    asm volatile("cp.async.cg.shared.global [%0], [%1], 16;" :: "r"(dst), "l"(src) : "memory");
}
__device__ __forceinline__ void cp_commit() {
    asm volatile("cp.async.commit_group;" ::: "memory");
}
__device__ __forceinline__ void cp_wait1() {
    asm volatile("cp.async.wait_group 1;" ::: "memory");
}
__device__ __forceinline__ void cp_wait0() {
    asm volatile("cp.async.wait_group 0;" ::: "memory");
}
__device__ __forceinline__ void ldm_x4(uint32_t& r0, uint32_t& r1, uint32_t& r2, uint32_t& r3,
                                       uint32_t addr) {
    asm volatile("ldmatrix.sync.aligned.m8n8.x4.shared.b16 {%0,%1,%2,%3}, [%4];"
                 : "=r"(r0), "=r"(r1), "=r"(r2), "=r"(r3) : "r"(addr));
}
__device__ __forceinline__ void ldm_x4_t(uint32_t& r0, uint32_t& r1, uint32_t& r2, uint32_t& r3,
                                         uint32_t addr) {
    asm volatile("ldmatrix.sync.aligned.m8n8.x4.trans.shared.b16 {%0,%1,%2,%3}, [%4];"
                 : "=r"(r0), "=r"(r1), "=r"(r2), "=r"(r3) : "r"(addr));
}
__device__ __forceinline__ void mma_bf16(float* c, const uint32_t* a, const uint32_t* b) {
    asm volatile("mma.sync.aligned.m16n8k16.row.col.f32.bf16.bf16.f32 "
                 "{%0,%1,%2,%3}, {%4,%5,%6,%7}, {%8,%9}, {%0,%1,%2,%3};"
                 : "+f"(c[0]), "+f"(c[1]), "+f"(c[2]), "+f"(c[3])
                 : "r"(a[0]), "r"(a[1]), "r"(a[2]), "r"(a[3]), "r"(b[0]), "r"(b[1]));
}
__device__ __forceinline__ void mma_bf16_2(float* c, const uint32_t* a, uint32_t b0, uint32_t b1) {
    asm volatile("mma.sync.aligned.m16n8k16.row.col.f32.bf16.bf16.f32 "
                 "{%0,%1,%2,%3}, {%4,%5,%6,%7}, {%8,%9}, {%0,%1,%2,%3};"
                 : "+f"(c[0]), "+f"(c[1]), "+f"(c[2]), "+f"(c[3])
                 : "r"(a[0]), "r"(a[1]), "r"(a[2]), "r"(a[3]), "r"(b0), "r"(b1));
}
// pack two fp32 into bf16x2: low half = f0, high half = f1
__device__ __forceinline__ uint32_t pack_bf16x2(float f0, float f1) {
    uint32_t r;
    asm("cvt.rn.bf16x2.f32 %0, %1, %2;" : "=r"(r) : "f"(f1), "f"(f0));
    return r;
}
__device__ __forceinline__ float bf16rt(float x) {
    return __bfloat162float(__float2bfloat16(x));
}

// ================= split kernels: fp32 -> (hi, lo) bf16 =================
__device__ __forceinline__ void split_one(const float* __restrict__ src,
                                          __nv_bfloat16* __restrict__ hi,
                                          __nv_bfloat16* __restrict__ lo, int i)
{
    float4 v = ((const float4*)src)[i];
    __nv_bfloat16 h0 = __float2bfloat16(v.x), h1 = __float2bfloat16(v.y);
    __nv_bfloat16 h2 = __float2bfloat16(v.z), h3 = __float2bfloat16(v.w);
    __nv_bfloat16 l0 = __float2bfloat16(v.x - __bfloat162float(h0));
    __nv_bfloat16 l1 = __float2bfloat16(v.y - __bfloat162float(h1));
    __nv_bfloat16 l2 = __float2bfloat16(v.z - __bfloat162float(h2));
    __nv_bfloat16 l3 = __float2bfloat16(v.w - __bfloat162float(h3));
    __nv_bfloat162* hp = (__nv_bfloat162*)hi;
    __nv_bfloat162* lp = (__nv_bfloat162*)lo;
    hp[i * 2 + 0] = __nv_bfloat162(h0, h1);
    hp[i * 2 + 1] = __nv_bfloat162(h2, h3);
    lp[i * 2 + 0] = __nv_bfloat162(l0, l1);
    lp[i * 2 + 1] = __nv_bfloat162(l2, l3);
}

__global__ __launch_bounds__(256) void split_kernel(
    const float* __restrict__ src, __nv_bfloat16* __restrict__ hi,
    __nv_bfloat16* __restrict__ lo, int n4)
{
    int i = blockIdx.x * blockDim.x + threadIdx.x;
    if (i >= n4) return;
    split_one(src, hi, lo, i);
}

// fused 4-weight split: blockIdx.y selects tensor
struct SplitSet {
    const float* src[4];
    __nv_bfloat16* hi[4];
    __nv_bfloat16* lo[4];
};
__global__ __launch_bounds__(256) void split4_kernel(SplitSet s, int n4)
{
    int i = blockIdx.x * blockDim.x + threadIdx.x;
    if (i >= n4) return;
    int t = blockIdx.y;
    split_one(s.src[t], s.hi[t], s.lo[t], i);
}

// ================= mma.sync GEMM core (CTA tile 128x128, BK=64) ==================
#define GBK        64
#define TILE_B     (128 * 128)
#define STAGE_B    (4 * TILE_B)
#define GEMM_SMEM  (2 * STAGE_B)

#define T_AHI 0
#define T_ALO (1 * TILE_B)
#define T_BHI (2 * TILE_B)
#define T_BLO (3 * TILE_B)

// Shared mainloop: computes acc for tile (m0, n0). MODE epilogues differ.
template<int MODE>
__device__ __forceinline__ void gemm_tile_body(
    const __nv_bfloat16* __restrict__ Ahi, const __nv_bfloat16* __restrict__ Alo,
    const __nv_bfloat16* __restrict__ Bhi, const __nv_bfloat16* __restrict__ Blo,
    float* __restrict__ C, __nv_bfloat16* __restrict__ Chi,
    __nv_bfloat16* __restrict__ Clo, float mul, int M, int N, int K,
    int m0, int n0, char* smem)
{
    const uint32_t sb = smem_u32(smem);
    const int tid = threadIdx.x;
    const int wid = tid >> 5;
    const int l   = tid & 31;
    const int wm  = wid & 3;
    const int wn  = wid >> 2;

    int lrow[4], ldst[4];
    #pragma unroll
    for (int i = 0; i < 4; i++) {
        int idx = tid + i * 256;
        int row = idx >> 3, c16 = idx & 7;
        lrow[i] = row;
        ldst[i] = row * 128 + ((c16 ^ (row & 7)) << 4);
    }

    auto issue_stage = [&](int c, int buf) {
        uint32_t s0 = sb + buf * STAGE_B;
        #pragma unroll
        for (int i = 0; i < 4; i++) {
            int row = lrow[i];
            int koff = c * GBK + ((tid + i * 256) & 7) * 8;
            cp_async16(s0 + T_AHI + ldst[i], Ahi + (size_t)(m0 + row) * K + koff);
            cp_async16(s0 + T_ALO + ldst[i], Alo + (size_t)(m0 + row) * K + koff);
            cp_async16(s0 + T_BHI + ldst[i], Bhi + (size_t)(n0 + row) * K + koff);
            cp_async16(s0 + T_BLO + ldst[i], Blo + (size_t)(n0 + row) * K + koff);
        }
        cp_commit();
    };

    const int a_rowoff = (l & 15);
    const int a_c16off = (l >> 4);
    const int b_rowoff = (l & 7) | ((l & 16) >> 1);
    const int b_c16off = (l >> 3) & 1;

    float acc[2][8][4];
    #pragma unroll
    for (int mi = 0; mi < 2; mi++)
        #pragma unroll
        for (int nj = 0; nj < 8; nj++)
            #pragma unroll
            for (int t = 0; t < 4; t++) acc[mi][nj][t] = 0.f;

    const int nchunks = K / GBK;
    issue_stage(0, 0);
    issue_stage(1, 1);

    for (int c = 0; c < nchunks; c++) {
        const int buf = c & 1;
        if (c < nchunks - 2) cp_wait1(); else cp_wait0();
        __syncthreads();

        const uint32_t s0 = sb + buf * STAGE_B;
        #pragma unroll
        for (int kk = 0; kk < 4; kk++) {
            uint32_t ahi[2][4], alo[2][4];
            #pragma unroll
            for (int mi = 0; mi < 2; mi++) {
                int row = wm * 32 + mi * 16 + a_rowoff;
                int c16 = kk * 2 + a_c16off;
                uint32_t ad = s0 + row * 128 + ((c16 ^ (row & 7)) << 4);
                ldm_x4(ahi[mi][0], ahi[mi][1], ahi[mi][2], ahi[mi][3], ad + T_AHI);
                ldm_x4(alo[mi][0], alo[mi][1], alo[mi][2], alo[mi][3], ad + T_ALO);
            }
            uint32_t bhi[8][2], blo[8][2];
            #pragma unroll
            for (int p = 0; p < 4; p++) {
                int row = wn * 64 + p * 16 + b_rowoff;
                int c16 = kk * 2 + b_c16off;
                uint32_t ad = s0 + row * 128 + ((c16 ^ (row & 7)) << 4);
                ldm_x4(bhi[2*p][0], bhi[2*p][1], bhi[2*p+1][0], bhi[2*p+1][1], ad + T_BHI);
                ldm_x4(blo[2*p][0], blo[2*p][1], blo[2*p+1][0], blo[2*p+1][1], ad + T_BLO);
            }
            #pragma unroll
            for (int mi = 0; mi < 2; mi++)
                #pragma unroll
                for (int nj = 0; nj < 8; nj++) {
                    mma_bf16(acc[mi][nj], ahi[mi], bhi[nj]);
                    mma_bf16(acc[mi][nj], ahi[mi], blo[nj]);
                    mma_bf16(acc[mi][nj], alo[mi], bhi[nj]);
                }
        }
        __syncthreads();
        if (c + 2 < nchunks) issue_stage(c + 2, buf);
    }

    const int er = l >> 2;
    const int ec = (l & 3) * 2;
    #pragma unroll
    for (int mi = 0; mi < 2; mi++) {
        int grow = m0 + wm * 32 + mi * 16 + er;
        #pragma unroll
        for (int nj = 0; nj < 8; nj++) {
            int gcol = n0 + wn * 64 + nj * 8 + ec;
            if (MODE == 0) {
                *(float2*)&C[(size_t)grow * N + gcol] =
                    make_float2(acc[mi][nj][0], acc[mi][nj][1]);
                *(float2*)&C[(size_t)(grow + 8) * N + gcol] =
                    make_float2(acc[mi][nj][2], acc[mi][nj][3]);
            } else {
                float c0 = acc[mi][nj][0] * mul, c1 = acc[mi][nj][1] * mul;
                float c2 = acc[mi][nj][2] * mul, c3 = acc[mi][nj][3] * mul;
                *(uint32_t*)&Chi[(size_t)grow * N + gcol]       = pack_bf16x2(c0, c1);
                *(uint32_t*)&Clo[(size_t)grow * N + gcol]       =
                    pack_bf16x2(c0 - bf16rt(c0), c1 - bf16rt(c1));
                *(uint32_t*)&Chi[(size_t)(grow + 8) * N + gcol] = pack_bf16x2(c2, c3);
                *(uint32_t*)&Clo[(size_t)(grow + 8) * N + gcol] =
                    pack_bf16x2(c2 - bf16rt(c2), c3 - bf16rt(c3));
            }
        }
    }
}

// MODE 0: fp32 output (final projection)
__global__ __launch_bounds__(256) void gemm_f32out_kernel(
    const __nv_bfloat16* __restrict__ Ahi, const __nv_bfloat16* __restrict__ Alo,
    const __nv_bfloat16* __restrict__ Bhi, const __nv_bfloat16* __restrict__ Blo,
    float* __restrict__ C, int M, int N, int K)
{
    extern __shared__ char smem[];
    gemm_tile_body<0>(Ahi, Alo, Bhi, Blo, C, nullptr, nullptr, 1.0f,
                      M, N, K, blockIdx.y * 128, blockIdx.x * 128, smem);
}

// Fused QKV: blockIdx.z selects weight set / output / scale
struct QKVSet {
    const __nv_bfloat16* bhi[3];
    const __nv_bfloat16* blo[3];
    __nv_bfloat16* chi[3];
    __nv_bfloat16* clo[3];
    float mul[3];
};
__global__ __launch_bounds__(256) void gemm_qkv_kernel(
    const __nv_bfloat16* __restrict__ Ahi, const __nv_bfloat16* __restrict__ Alo,
    QKVSet s, int M, int N, int K)
{
    extern __shared__ char smem[];
    const int z = blockIdx.z;
    gemm_tile_body<1>(Ahi, Alo, s.bhi[z], s.blo[z], nullptr, s.chi[z], s.clo[z],
                      s.mul[z], M, N, K, blockIdx.y * 128, blockIdx.x * 128, smem);
}

// ============================================================
// Tensor-core flash attention (causal) — inputs pre-split bf16 hi/lo.
// Block: 128 threads (4 warps); BQ=64, BKV=64, hd=128.
// smem: 6 tiles of 64 rows x 128 bf16 (256B rows, XOR-swizzled), 96 KB.
// Longest blocks (large qt) launch first: qt = gridDim.x-1-blockIdx.x.
// ============================================================
#define FT_QHI 0
#define FT_QLO 16384
#define FT_KHI 32768
#define FT_KLO 49152
#define FT_VHI 65536
#define FT_VLO 81920
#define FLASH_TC_SMEM 98304

__device__ __forceinline__ uint32_t fsw(int row, int c16) {
    return (uint32_t)(row * 256 + ((c16 ^ ((row & 7) << 1)) << 4));
}

__global__ __launch_bounds__(128) void flash_attn_tc_kernel(
    const __nv_bfloat16* __restrict__ qhi, const __nv_bfloat16* __restrict__ qlo,
    const __nv_bfloat16* __restrict__ khi, const __nv_bfloat16* __restrict__ klo,
    const __nv_bfloat16* __restrict__ vhi, const __nv_bfloat16* __restrict__ vlo,
    __nv_bfloat16* __restrict__ ohi, __nv_bfloat16* __restrict__ olo)
{
    extern __shared__ char fsm[];
    const uint32_t sb = smem_u32(fsm);
    const int tid = threadIdx.x;
    const int wid = tid >> 5;
    const int l   = tid & 31;
    const int qt = gridDim.x - 1 - blockIdx.x;   // longest-first scheduling
    const int h  = blockIdx.y;
    const int b  = blockIdx.z;
    const int q0 = qt * 64;

    // thread's cp.async slots: 8 chunks per 64x128 tile
    const size_t gq = ((size_t)b * SEQ + q0) * DMODEL + h * HDIM;
    #pragma unroll
    for (int i = 0; i < 8; i++) {
        int idx = tid + i * 128;
        int row = idx >> 4, c16 = idx & 15;
        uint32_t off = fsw(row, c16);
        size_t src = gq + (size_t)row * DMODEL + c16 * 8;
        cp_async16(sb + FT_QHI + off, qhi + src);
        cp_async16(sb + FT_QLO + off, qlo + src);
    }
    cp_commit();

    const int r  = l >> 2;
    const int cq = l & 3;

    const int a_rowoff = (l & 15);
    const int a_c16off = (l >> 4);
    const int b_rowoff = (l & 7) | ((l & 16) >> 1);
    const int b_c16off = (l >> 3) & 1;

    float m0v = -1e30f, m1v = -1e30f, l0v = 0.f, l1v = 0.f;
    float O[16][4];
    #pragma unroll
    for (int g = 0; g < 16; g++)
        #pragma unroll
        for (int t = 0; t < 4; t++) O[g][t] = 0.f;

    for (int kt = 0; kt <= qt; kt++) {
        __syncthreads();   // previous iteration's readers done before overwrite
        const size_t gkv = ((size_t)b * SEQ + kt * 64) * DMODEL + h * HDIM;
        #pragma unroll
        for (int i = 0; i < 8; i++) {
            int idx = tid + i * 128;
            int row = idx >> 4, c16 = idx & 15;
            uint32_t off = fsw(row, c16);
            size_t src = gkv + (size_t)row * DMODEL + c16 * 8;
            cp_async16(sb + FT_KHI + off, khi + src);
            cp_async16(sb + FT_KLO + off, klo + src);
            cp_async16(sb + FT_VHI + off, vhi + src);
            cp_async16(sb + FT_VLO + off, vlo + src);
        }
        cp_commit();
        cp_wait0();
        __syncthreads();

        // ---- scores S = Qs @ K^T (3-term bf16) ----
        float s[8][4];
        #pragma unroll
        for (int nj = 0; nj < 8; nj++)
            #pragma unroll
            for (int t = 0; t < 4; t++) s[nj][t] = 0.f;

        #pragma unroll
        for (int j = 0; j < 8; j++) {
            int arow = wid * 16 + a_rowoff;
            uint32_t aad = sb + fsw(arow, 2 * j + a_c16off);
            uint32_t ah[4], al_[4];
            ldm_x4(ah[0], ah[1], ah[2], ah[3], aad + FT_QHI);
            ldm_x4(al_[0], al_[1], al_[2], al_[3], aad + FT_QLO);

            uint32_t bh[8][2], bl[8][2];
            #pragma unroll
            for (int p = 0; p < 4; p++) {
                int brow = p * 16 + b_rowoff;
                uint32_t bad = sb + fsw(brow, 2 * j + b_c16off);
                ldm_x4(bh[2*p][0], bh[2*p][1], bh[2*p+1][0], bh[2*p+1][1], bad + FT_KHI);
                ldm_x4(bl[2*p][0], bl[2*p][1], bl[2*p+1][0], bl[2*p+1][1], bad + FT_KLO);
            }
            #pragma unroll
            for (int nj = 0; nj < 8; nj++) {
                mma_bf16(s[nj], ah,  bh[nj]);
                mma_bf16(s[nj], ah,  bl[nj]);
                mma_bf16(s[nj], al_, bh[nj]);
            }
        }

        // ---- causal mask (diagonal tile only) ----
        if (kt == qt) {
            #pragma unroll
            for (int nj = 0; nj < 8; nj++)
                #pragma unroll
                for (int t = 0; t < 4; t++) {
                    int coll = nj * 8 + 2 * cq + (t & 1);
                    int rowl = wid * 16 + r + ((t >> 1) << 3);
                    if (coll > rowl) s[nj][t] = -1e30f;
                }
        }

        // ---- online softmax ----
        float mx0 = -1e30f, mx1 = -1e30f;
        #pragma unroll
        for (int nj = 0; nj < 8; nj++) {
            mx0 = fmaxf(mx0, fmaxf(s[nj][0], s[nj][1]));
            mx1 = fmaxf(mx1, fmaxf(s[nj][2], s[nj][3]));
        }
        mx0 = fmaxf(mx0, __shfl_xor_sync(0xffffffffu, mx0, 1));
        mx0 = fmaxf(mx0, __shfl_xor_sync(0xffffffffu, mx0, 2));
        mx1 = fmaxf(mx1, __shfl_xor_sync(0xffffffffu, mx1, 1));
        mx1 = fmaxf(mx1, __shfl_xor_sync(0xffffffffu, mx1, 2));

        float mn0 = fmaxf(m0v, mx0), mn1 = fmaxf(m1v, mx1);
        float al0 = __expf(m0v - mn0), al1 = __expf(m1v - mn1);
        m0v = mn0; m1v = mn1;

        #pragma unroll
        for (int g = 0; g < 16; g++) {
            O[g][0] *= al0; O[g][1] *= al0;
            O[g][2] *= al1; O[g][3] *= al1;
        }

        float rs0 = 0.f, rs1 = 0.f;
        #pragma unroll
        for (int nj = 0; nj < 8; nj++) {
            s[nj][0] = __expf(s[nj][0] - mn0);
            s[nj][1] = __expf(s[nj][1] - mn0);
            s[nj][2] = __expf(s[nj][2] - mn1);
            s[nj][3] = __expf(s[nj][3] - mn1);
            rs0 += s[nj][0] + s[nj][1];
            rs1 += s[nj][2] + s[nj][3];
        }
        rs0 += __shfl_xor_sync(0xffffffffu, rs0, 1);
        rs0 += __shfl_xor_sync(0xffffffffu, rs0, 2);
        rs1 += __shfl_xor_sync(0xffffffffu, rs1, 1);
        rs1 += __shfl_xor_sync(0xffffffffu, rs1, 2);
        l0v = l0v * al0 + rs0;
        l1v = l1v * al1 + rs1;

        // ---- O += P @ V (3-term bf16) ----
        #pragma unroll
        for (int j = 0; j < 4; j++) {
            uint32_t pah[4], pal[4];
            {
                float p00 = s[2*j][0],   p01 = s[2*j][1];
                float p02 = s[2*j][2],   p03 = s[2*j][3];
                float p10 = s[2*j+1][0], p11 = s[2*j+1][1];
                float p12 = s[2*j+1][2], p13 = s[2*j+1][3];
                pah[0] = pack_bf16x2(p00, p01);
                pah[1] = pack_bf16x2(p02, p03);
                pah[2] = pack_bf16x2(p10, p11);
                pah[3] = pack_bf16x2(p12, p13);
                pal[0] = pack_bf16x2(p00 - bf16rt(p00), p01 - bf16rt(p01));
                pal[1] = pack_bf16x2(p02 - bf16rt(p02), p03 - bf16rt(p03));
                pal[2] = pack_bf16x2(p10 - bf16rt(p10), p11 - bf16rt(p11));
                pal[3] = pack_bf16x2(p12 - bf16rt(p12), p13 - bf16rt(p13));
            }
            #pragma unroll
            for (int g = 0; g < 8; g++) {
                int vrow = j * 16 + (l & 15);
                uint32_t vad = sb + fsw(vrow, 2 * g + (l >> 4));
                uint32_t vh0, vh1, vh2, vh3, vl0, vl1, vl2, vl3;
                ldm_x4_t(vh0, vh1, vh2, vh3, vad + FT_VHI);
                ldm_x4_t(vl0, vl1, vl2, vl3, vad + FT_VLO);
                mma_bf16_2(O[2*g],     pah, vh0, vh1);
                mma_bf16_2(O[2*g],     pah, vl0, vl1);
                mma_bf16_2(O[2*g],     pal, vh0, vh1);
                mma_bf16_2(O[2*g + 1], pah, vh2, vh3);
                mma_bf16_2(O[2*g + 1], pah, vl2, vl3);
                mma_bf16_2(O[2*g + 1], pal, vh2, vh3);
            }
        }
    }

    // ---- epilogue: divide by l, write hi/lo bf16 ----
    const float i0 = 1.0f / l0v;
    const float i1 = 1.0f / l1v;
    const size_t obase = ((size_t)b * SEQ + q0 + wid * 16 + r) * DMODEL + h * HDIM;
    #pragma unroll
    for (int g = 0; g < 16; g++) {
        int col = g * 8 + 2 * cq;
        float a0 = O[g][0] * i0, a1 = O[g][1] * i0;
        float a2 = O[g][2] * i1, a3 = O[g][3] * i1;
        *(uint32_t*)&ohi[obase + col] = pack_bf16x2(a0, a1);
        *(uint32_t*)&olo[obase + col] = pack_bf16x2(a0 - bf16rt(a0), a1 - bf16rt(a1));
        *(uint32_t*)&ohi[obase + (size_t)8 * DMODEL + col] = pack_bf16x2(a2, a3);
        *(uint32_t*)&olo[obase + (size_t)8 * DMODEL + col] =
            pack_bf16x2(a2 - bf16rt(a2), a3 - bf16rt(a3));
    }
}

// ============================================================
// launcher
// ============================================================
extern "C" void kernel_launch(void* const* d_in, const int* in_sizes, int n_in,
                              void* d_out, int out_size)
{
    const float* x  = (const float*)d_in[0];
    const float* Wq = (const float*)d_in[1];
    const float* Wk = (const float*)d_in[2];
    const float* Wv = (const float*)d_in[3];
    const float* Wp = (const float*)d_in[4];
    float* out = (float*)d_out;

    void *qhi, *qlo, *khi, *klo, *vhi, *vlo, *aohi, *aolo;
    cudaGetSymbolAddress(&qhi,  g_qhi);  cudaGetSymbolAddress(&qlo,  g_qlo);
    cudaGetSymbolAddress(&khi,  g_khi);  cudaGetSymbolAddress(&klo,  g_klo);
    cudaGetSymbolAddress(&vhi,  g_vhi);  cudaGetSymbolAddress(&vlo,  g_vlo);
    cudaGetSymbolAddress(&aohi, g_aohi); cudaGetSymbolAddress(&aolo, g_aolo);

    void *xhi, *xlo;
    void *wqhi, *wqlo, *wkhi, *wklo, *wvhi, *wvlo, *wphi, *wplo;
    cudaGetSymbolAddress(&xhi,  g_xhi);  cudaGetSymbolAddress(&xlo,  g_xlo);
    cudaGetSymbolAddress(&wqhi, g_wqhi); cudaGetSymbolAddress(&wqlo, g_wqlo);
    cudaGetSymbolAddress(&wkhi, g_wkhi); cudaGetSymbolAddress(&wklo, g_wklo);
    cudaGetSymbolAddress(&wvhi, g_wvhi); cudaGetSymbolAddress(&wvlo, g_wvlo);
    cudaGetSymbolAddress(&wphi, g_wphi); cudaGetSymbolAddress(&wplo, g_wplo);

    cudaFuncSetAttribute(flash_attn_tc_kernel,
                         cudaFuncAttributeMaxDynamicSharedMemorySize, FLASH_TC_SMEM);
    cudaFuncSetAttribute(gemm_f32out_kernel,
                         cudaFuncAttributeMaxDynamicSharedMemorySize, GEMM_SMEM);
    cudaFuncSetAttribute(gemm_qkv_kernel,
                         cudaFuncAttributeMaxDynamicSharedMemorySize, GEMM_SMEM);

    const int nx4 = (MROWS * DMODEL) / 4;
    const int nw4 = (DMODEL * DMODEL) / 4;

    // input split (x) + fused 4-weight split
    split_kernel<<<(nx4 + 255) / 256, 256>>>(x, (__nv_bfloat16*)xhi, (__nv_bfloat16*)xlo, nx4);
    {
        SplitSet ss;
        ss.src[0] = Wq; ss.hi[0] = (__nv_bfloat16*)wqhi; ss.lo[0] = (__nv_bfloat16*)wqlo;
        ss.src[1] = Wk; ss.hi[1] = (__nv_bfloat16*)wkhi; ss.lo[1] = (__nv_bfloat16*)wklo;
        ss.src[2] = Wv; ss.hi[2] = (__nv_bfloat16*)wvhi; ss.lo[2] = (__nv_bfloat16*)wvlo;
        ss.src[3] = Wp; ss.hi[3] = (__nv_bfloat16*)wphi; ss.lo[3] = (__nv_bfloat16*)wplo;
        dim3 sg((nw4 + 255) / 256, 4);
        split4_kernel<<<sg, 256>>>(ss, nw4);
    }

    const float scale = 0.08838834764831845f;  // 1/sqrt(128), folded into Q

    // fused QKV projection (one launch, 1536 CTAs)
    {
        QKVSet qs;
        qs.bhi[0] = (const __nv_bfloat16*)wqhi; qs.blo[0] = (const __nv_bfloat16*)wqlo;
        qs.chi[0] = (__nv_bfloat16*)qhi;        qs.clo[0] = (__nv_bfloat16*)qlo;
        qs.mul[0] = scale;
        qs.bhi[1] = (const __nv_bfloat16*)wkhi; qs.blo[1] = (const __nv_bfloat16*)wklo;
        qs.chi[1] = (__nv_bfloat16*)khi;        qs.clo[1] = (__nv_bfloat16*)klo;
        qs.mul[1] = 1.0f;
        qs.bhi[2] = (const __nv_bfloat16*)wvhi; qs.blo[2] = (const __nv_bfloat16*)wvlo;
        qs.chi[2] = (__nv_bfloat16*)vhi;        qs.clo[2] = (__nv_bfloat16*)vlo;
        qs.mul[2] = 1.0f;
        dim3 qg(DMODEL / 128, MROWS / 128, 3);   // (16, 32, 3)
        gemm_qkv_kernel<<<qg, 256, GEMM_SMEM>>>(
            (const __nv_bfloat16*)xhi, (const __nv_bfloat16*)xlo,
            qs, MROWS, DMODEL, DMODEL);
    }

    dim3 fgrid(SEQ / 64, NHEAD, BATCH);      // (32, 16, 2)
    flash_attn_tc_kernel<<<fgrid, 128, FLASH_TC_SMEM>>>(
        (const __nv_bfloat16*)qhi, (const __nv_bfloat16*)qlo,
        (const __nv_bfloat16*)khi, (const __nv_bfloat16*)klo,
        (const __nv_bfloat16*)vhi, (const __nv_bfloat16*)vlo,
        (__nv_bfloat16*)aohi, (__nv_bfloat16*)aolo);

    dim3 ggrid(DMODEL / 128, MROWS / 128);   // (16, 32)
    gemm_f32out_kernel<<<ggrid, 256, GEMM_SMEM>>>(
        (const __nv_bfloat16*)aohi, (const __nv_bfloat16*)aolo,
        (const __nv_bfloat16*)wphi, (const __nv_bfloat16*)wplo,
        out, MROWS, DMODEL, DMODEL);
}